// round 6
// baseline (speedup 1.0000x reference)
#include <cuda_runtime.h>
#include <cuda_fp16.h>
#include <cstdint>

#define TOK   2048
#define CDIM  2048
#define NHEAD 32
#define DDIM  64
#define KR    1024

#define CTOK  256            // tokens per CTA (route)
#define NTPM  128            // 8-col n-tiles per matrix
#define NTT   (3 * NTPM)     // 384 n-tiles (q,k,v)
#define GSZ   16             // n-tiles per pipeline group
#define NGRP  (NTT / GSZ)    // 24
#define NT_B  1024           // bytes per n-tile (hi only): 4 ks x 32 lanes x 8B
#define GRP_B (GSZ * NT_B)   // 16 KB

#define SM_XB    (CTOK * 68 * 4)              // 69632 (x tile, pitch 68)
#define SM_NORM  (SM_XB + 2 * GRP_B)          // 102400
#define SM_TOTAL (SM_NORM + CTOK * 4)         // 103424 -> 2 CTAs/SM

// sound screening bound:  eps = EPSC * ||x_t|| * maxB  + SLACK
#define EPSC  1.0254e-3f     // 1.05 * 2^-10
#define SLACK 3.0e-4f

__device__ int g_qid[NHEAD * TOK];
__device__ int g_kid[NHEAD * TOK];
__device__ int g_vid[NHEAD * TOK];
__device__ int g_row[NHEAD * TOK];
__device__ float g_maxB[3 * NHEAD];
__device__ int g_flagcnt[3 * NHEAD];
__device__ int g_flaglist[3 * NHEAD * TOK];
// W hi-split fp16, fragment-major: [mat][head][ntl][ks][lane][8B]
__device__ __align__(16) uint8_t g_whf[(size_t)3 * NHEAD * NTPM * NT_B];   // 12 MB

// ---------------- helpers ----------------
static __device__ __forceinline__ uint32_t s2u(const void* p) {
    uint32_t a;
    asm("{ .reg .u64 t; cvta.to.shared.u64 t, %1; cvt.u32.u64 %0, t; }"
        : "=r"(a) : "l"(p));
    return a;
}
static __device__ __forceinline__ uint32_t h2u(__half2 h) {
    uint32_t u; asm("mov.b32 %0, %1;" : "=r"(u) : "r"(*(uint32_t*)&h)); return u;
}
static __device__ __forceinline__ void mma_f16(float* d, const uint32_t* a,
                                               uint32_t b0, uint32_t b1) {
    asm volatile("mma.sync.aligned.m16n8k16.row.col.f32.f16.f16.f32 "
                 "{%0,%1,%2,%3}, {%4,%5,%6,%7}, {%8,%9}, {%0,%1,%2,%3};"
                 : "+f"(d[0]), "+f"(d[1]), "+f"(d[2]), "+f"(d[3])
                 : "r"(a[0]), "r"(a[1]), "r"(a[2]), "r"(a[3]),
                   "r"(b0), "r"(b1));
}
static __device__ __forceinline__ void cp16(uint32_t d, const void* s) {
    asm volatile("cp.async.cg.shared.global [%0], [%1], 16;"
                 :: "r"(d), "l"(s) : "memory");
}
#define CP_COMMIT() asm volatile("cp.async.commit_group;" ::: "memory")
#define CP_WAIT1()  asm volatile("cp.async.wait_group 1;" ::: "memory")
#define CP_WAIT0()  asm volatile("cp.async.wait_group 0;" ::: "memory")

// ---------------------------------------------------------------------------
// Prepass A: W -> fp16(hi), fragment-major.
// id bits: lane[0:5) ks[5:7) ntl[7:14) head[14:19) mat[19:21)
// ---------------------------------------------------------------------------
__global__ __launch_bounds__(256) void split_w_kernel(
    const float* __restrict__ wq, const float* __restrict__ wk,
    const float* __restrict__ wv)
{
    uint32_t id = blockIdx.x * 256u + threadIdx.x;
    uint32_t lane = id & 31u;
    uint32_t ks   = (id >> 5) & 3u;
    uint32_t ntl  = (id >> 7) & 127u;
    uint32_t head = (id >> 14) & 31u;
    uint32_t mat  = id >> 19;
    const float* W = (mat == 0) ? wq : (mat == 1) ? wk : wv;
    int col = (int)(ntl * 8 + (lane >> 2));
    int k0  = (int)(ks * 16 + 2 * (lane & 3));
    size_t off = ((size_t)head * KR + col) * DDIM + k0;
    float2 v0 = *reinterpret_cast<const float2*>(W + off);
    float2 v1 = *reinterpret_cast<const float2*>(W + off + 8);
    uint2 o;
    o.x = h2u(__float22half2_rn(v0));
    o.y = h2u(__float22half2_rn(v1));
    *reinterpret_cast<uint2*>(g_whf + (size_t)id * 8) = o;
}

// ---------------------------------------------------------------------------
// Prepass B: per (mat,head) max column norm of W; also zero flag counters.
// grid = 96, block = 256.
// ---------------------------------------------------------------------------
__global__ __launch_bounds__(256) void bnorm_kernel(
    const float* __restrict__ wq, const float* __restrict__ wk,
    const float* __restrict__ wv)
{
    __shared__ float wmax[8];
    const int b = blockIdx.x, tid = threadIdx.x;
    const int mat = b >> 5, head = b & 31;
    if (tid == 0) g_flagcnt[b] = 0;
    const float* W = ((mat == 0) ? wq : (mat == 1) ? wk : wv)
                     + (size_t)head * KR * DDIM;
    float mx = 0.f;
    for (int col = tid; col < KR; col += 256) {
        const float4* r = reinterpret_cast<const float4*>(W + (size_t)col * DDIM);
        float s = 0.f;
        #pragma unroll
        for (int i = 0; i < 16; ++i) {
            float4 v = r[i];
            s += v.x * v.x + v.y * v.y + v.z * v.z + v.w * v.w;
        }
        mx = fmaxf(mx, s);
    }
    #pragma unroll
    for (int off = 16; off > 0; off >>= 1)
        mx = fmaxf(mx, __shfl_xor_sync(0xffffffffu, mx, off, 32));
    if ((tid & 31) == 0) wmax[tid >> 5] = mx;
    __syncthreads();
    if (tid == 0) {
        float m = wmax[0];
        #pragma unroll
        for (int w = 1; w < 8; ++w) m = fmaxf(m, wmax[w]);
        g_maxB[b] = sqrtf(m);
    }
}

// ---------------------------------------------------------------------------
// Pass 1: hh-only fp16 mma.sync with certified top-2 screening.
// grid = (8, 32), block = 256 (8 warps), 2 CTAs/SM.
// ---------------------------------------------------------------------------
__global__ __launch_bounds__(256, 2) void tc_route_kernel(const float* __restrict__ x)
{
    extern __shared__ uint8_t smem[];
    float* xs = reinterpret_cast<float*>(smem);
    float* xnorm_s = reinterpret_cast<float*>(smem + SM_NORM);
    const uint32_t sbB = s2u(smem) + SM_XB;

    const int tid = threadIdx.x, lane = tid & 31, wid = tid >> 5;
    const int m = blockIdx.y;
    const int t0 = blockIdx.x * CTOK;

    // stage x tile [CTOK][64] (pitch 68)
    for (int i = tid; i < CTOK * 16; i += 256) {
        int t = i >> 4, c = i & 15;
        float4 v = *reinterpret_cast<const float4*>(
            x + (size_t)(t0 + t) * CDIM + m * DDIM + c * 4);
        *reinterpret_cast<float4*>(&xs[t * 68 + c * 4]) = v;
    }
    __syncthreads();

    // per-token x norm (for the screening bound)
    {
        const float4* r = reinterpret_cast<const float4*>(&xs[tid * 68]);
        float s = 0.f;
        #pragma unroll
        for (int i = 0; i < 16; ++i) {
            float4 v = r[i];
            s += v.x * v.x + v.y * v.y + v.z * v.z + v.w * v.w;
        }
        xnorm_s[tid] = sqrtf(s);
    }

    // A fragments, hi only: 2 m-tiles x 4 ksteps x 4 regs (packed half2)
    uint32_t ah[2][4][4];
    const int r0 = wid * 32 + (lane >> 2);
    #pragma unroll
    for (int mt = 0; mt < 2; ++mt)
        #pragma unroll
        for (int ks = 0; ks < 4; ++ks)
            #pragma unroll
            for (int e = 0; e < 4; ++e) {
                int row = r0 + mt * 16 + (e & 1) * 8;
                int kc  = ks * 16 + 2 * (lane & 3) + (e >> 1) * 8;
                float2 v = *reinterpret_cast<const float2*>(&xs[row * 68 + kc]);
                ah[mt][ks][e] = h2u(__float22half2_rn(v));
            }
    __syncthreads();   // xnorm visible, xs no longer mutated

    auto stage = [&](int g2) {
        int F0 = g2 * GSZ;
        int mat = F0 >> 7, ntl0 = F0 & (NTPM - 1);
        const uint8_t* src = g_whf
            + (((size_t)mat * NHEAD + m) * NTPM + ntl0) * NT_B + tid * 16;
        uint32_t dst = sbB + (uint32_t)(g2 & 1) * GRP_B + tid * 16;
        #pragma unroll
        for (int j = 0; j < 4; ++j)
            cp16(dst + j * 4096u, src + (size_t)j * 4096);
    };

    // per-slot top-2 state (4 slots = 2 mtiles x 2 rows)
    float max1[4], max2[4]; int bidx[4];
    #pragma unroll
    for (int s = 0; s < 4; ++s) {
        max1[s] = -3.402823466e38f; max2[s] = -3.402823466e38f; bidx[s] = 0;
    }

    stage(0); CP_COMMIT();

    #pragma unroll 1
    for (int g = 0; g < NGRP; ++g) {
        if (g + 1 < NGRP) { stage(g + 1); CP_COMMIT(); CP_WAIT1(); }
        else              { CP_WAIT0(); }
        __syncthreads();

        const uint32_t bb = sbB + (uint32_t)(g & 1) * GRP_B + (uint32_t)lane * 8u;
        #pragma unroll 1
        for (int ntg = 0; ntg < GSZ; ++ntg) {
            const int F = g * GSZ + ntg;
            float d0[4] = {0.f, 0.f, 0.f, 0.f};
            float d1[4] = {0.f, 0.f, 0.f, 0.f};
            const uint32_t tb = bb + (uint32_t)ntg * NT_B;
            #pragma unroll
            for (int ks = 0; ks < 4; ++ks) {
                uint32_t b0, b1;
                asm volatile("ld.shared.v2.b32 {%0,%1}, [%2];"
                             : "=r"(b0), "=r"(b1) : "r"(tb + ks * 256u));
                mma_f16(d0, ah[0][ks], b0, b1);
                mma_f16(d1, ah[1][ks], b0, b1);
            }
            const int cb = (F & (NTPM - 1)) * 8 + 2 * (lane & 3);
            // top-2 update, ascending col order
            #pragma unroll
            for (int e = 0; e < 8; ++e) {
                float v = (e < 4) ? d0[e] : d1[e - 4];
                int s = ((e >> 2) << 1) | ((e >> 1) & 1);
                int col = cb + (e & 1);
                bool gt = v > max1[s];
                max2[s] = gt ? max1[s] : fmaxf(max2[s], v);
                bidx[s] = gt ? col : bidx[s];
                max1[s] = gt ? v : max1[s];
            }

            if (((F + 1) & (NTPM - 1)) == 0) {      // matrix boundary
                const int mat = F >> 7;
                int* G = (mat == 0) ? g_qid : (mat == 1) ? g_kid : g_vid;
                const float mbv = g_maxB[mat * 32 + m];
                #pragma unroll
                for (int s = 0; s < 4; ++s) {
                    float m1 = max1[s], m2 = max2[s]; int bi = bidx[s];
                    #pragma unroll
                    for (int off = 1; off <= 2; off <<= 1) {
                        float o1 = __shfl_xor_sync(0xffffffffu, m1, off, 32);
                        float o2 = __shfl_xor_sync(0xffffffffu, m2, off, 32);
                        int   oi = __shfl_xor_sync(0xffffffffu, bi, off, 32);
                        bool bw = (o1 > m1) || (o1 == m1 && oi < bi);
                        float nm2 = bw ? fmaxf(m1, o2) : fmaxf(m2, o1);
                        m1 = bw ? o1 : m1; bi = bw ? oi : bi; m2 = nm2;
                    }
                    if ((lane & 3) == 0) {
                        int row = wid * 32 + (lane >> 2) + (s >> 1) * 16 + (s & 1) * 8;
                        G[m * TOK + t0 + row] = bi;
                        float eps = EPSC * xnorm_s[row] * mbv + SLACK;
                        if (m1 - m2 < 2.f * eps) {
                            int p = atomicAdd(&g_flagcnt[mat * 32 + m], 1);
                            g_flaglist[(mat * 32 + m) * TOK + p] = t0 + row;
                        }
                    }
                    max1[s] = -3.402823466e38f;
                    max2[s] = -3.402823466e38f;
                    bidx[s] = 0;
                }
            }
        }
        __syncthreads();
    }
}

// ---------------------------------------------------------------------------
// Pass 2: exact fp32 argmax for flagged tokens.
// grid = (96, 4): slice s handles list positions  s, s+4, s+8, ...
// 8 threads per token (p = tid&7 -> 8 cols per chunk-part), 32 token slots.
// ---------------------------------------------------------------------------
__global__ __launch_bounds__(256) void refine_kernel(
    const float* __restrict__ x, const float* __restrict__ wq,
    const float* __restrict__ wk, const float* __restrict__ wv)
{
    __shared__ float xs_r[32 * 68];   // 8704 B
    __shared__ float wch[64 * 68];    // 17408 B

    const int b = blockIdx.x, s = blockIdx.y, tid = threadIdx.x;
    const int mat = b >> 5, head = b & 31;
    const int cnt = g_flagcnt[b];
    if (s >= cnt) return;   // uniform per CTA

    const float* W = ((mat == 0) ? wq : (mat == 1) ? wk : wv)
                     + (size_t)head * KR * DDIM;
    int* G = (mat == 0) ? g_qid : (mat == 1) ? g_kid : g_vid;
    const int* list = g_flaglist + b * TOK;

    const int tt = tid >> 3, p = tid & 7;

    for (int batch = 0; s + 4 * (batch * 32) < cnt; ++batch) {
        __syncthreads();   // previous batch fully done with xs_r
        // load up to 32 flagged x slices
        for (int i = tid; i < 32 * 16; i += 256) {
            int t = i >> 4, c4 = i & 15;
            int pos = s + 4 * (batch * 32 + t);
            if (pos < cnt) {
                int token = list[pos];
                float4 v = *reinterpret_cast<const float4*>(
                    x + (size_t)token * CDIM + head * DDIM + c4 * 4);
                *reinterpret_cast<float4*>(&xs_r[t * 68 + c4 * 4]) = v;
            }
        }
        const int mypos = s + 4 * (batch * 32 + tt);
        const bool valid = mypos < cnt;

        float best = -3.402823466e38f;
        int bcol = 0x7fffffff;

        for (int c = 0; c < 16; ++c) {
            __syncthreads();
            for (int i = tid; i < 1024; i += 256) {
                int cl = i >> 4, c4 = i & 15;
                float4 v = *reinterpret_cast<const float4*>(
                    W + (size_t)(c * 64 + cl) * DDIM + c4 * 4);
                *reinterpret_cast<float4*>(&wch[cl * 68 + c4 * 4]) = v;
            }
            __syncthreads();

            float acc[8] = {0.f, 0.f, 0.f, 0.f, 0.f, 0.f, 0.f, 0.f};
            const float* xr = &xs_r[tt * 68];
            #pragma unroll
            for (int kh = 0; kh < 2; ++kh) {
                float2 xv[16];
                #pragma unroll
                for (int kk = 0; kk < 16; ++kk)
                    xv[kk] = *reinterpret_cast<const float2*>(&xr[kh * 32 + kk * 2]);
                #pragma unroll
                for (int j = 0; j < 8; ++j) {
                    const float2* wr = reinterpret_cast<const float2*>(
                        &wch[(p * 8 + j) * 68 + kh * 32]);
                    #pragma unroll
                    for (int kk = 0; kk < 16; ++kk) {
                        float2 w = wr[kk];
                        acc[j] = fmaf(xv[kk].x, w.x, acc[j]);
                        acc[j] = fmaf(xv[kk].y, w.y, acc[j]);
                    }
                }
            }
            #pragma unroll
            for (int j = 0; j < 8; ++j) {
                int col = c * 64 + p * 8 + j;
                if (acc[j] > best || (acc[j] == best && col < bcol)) {
                    best = acc[j]; bcol = col;
                }
            }
        }

        // reduce over the 8 threads of this token
        #pragma unroll
        for (int off = 1; off <= 4; off <<= 1) {
            float ov = __shfl_xor_sync(0xffffffffu, best, off, 32);
            int   oc = __shfl_xor_sync(0xffffffffu, bcol, off, 32);
            if (ov > best || (ov == best && oc < bcol)) { best = ov; bcol = oc; }
        }
        if (valid && p == 0) {
            int token = list[mypos];
            G[head * TOK + token] = bcol;
        }
    }
}

// ---------------------------------------------------------------------------
// tau matching via bucketed counting sort. grid=NHEAD, block=256.
// ---------------------------------------------------------------------------
__global__ __launch_bounds__(256) void match_kernel()
{
    __shared__ int cnt[KR];
    __shared__ int bstart[KR + 1];
    __shared__ int kpos[TOK];
    __shared__ int wsum[8];

    const int m = blockIdx.x, tid = threadIdx.x;
    const int lane = tid & 31, wid = tid >> 5;
    const int base = m * TOK;

    for (int i = tid; i < KR; i += 256) cnt[i] = 0;
    __syncthreads();
    for (int t = tid; t < TOK; t += 256) atomicAdd(&cnt[g_kid[base + t]], 1);
    __syncthreads();

    int c0 = cnt[tid * 4], c1 = cnt[tid * 4 + 1],
        c2 = cnt[tid * 4 + 2], c3 = cnt[tid * 4 + 3];
    int tot = c0 + c1 + c2 + c3;
    int incl = tot;
    #pragma unroll
    for (int off = 1; off < 32; off <<= 1) {
        int nv = __shfl_up_sync(0xffffffffu, incl, off, 32);
        if (lane >= off) incl += nv;
    }
    if (lane == 31) wsum[wid] = incl;
    __syncthreads();
    if (tid == 0) {
        int r = 0;
        #pragma unroll
        for (int w = 0; w < 8; ++w) { int v = wsum[w]; wsum[w] = r; r += v; }
    }
    __syncthreads();
    int ex = incl - tot + wsum[wid];
    bstart[tid * 4]     = ex;
    bstart[tid * 4 + 1] = ex + c0;
    bstart[tid * 4 + 2] = ex + c0 + c1;
    bstart[tid * 4 + 3] = ex + c0 + c1 + c2;
    if (tid == 0) bstart[KR] = TOK;
    __syncthreads();
    cnt[tid * 4]     = ex;
    cnt[tid * 4 + 1] = ex + c0;
    cnt[tid * 4 + 2] = ex + c0 + c1;
    cnt[tid * 4 + 3] = ex + c0 + c1 + c2;
    __syncthreads();

    for (int t = tid; t < TOK; t += 256) {
        int k = g_kid[base + t];
        int p = atomicAdd(&cnt[k], 1);
        kpos[p] = t;
    }
    __syncthreads();

    for (int b = tid; b < KR; b += 256) {
        int lo = bstart[b], hi = bstart[b + 1];
        for (int i = lo + 1; i < hi; ++i) {
            int v = kpos[i], j = i - 1;
            while (j >= lo && kpos[j] > v) { kpos[j + 1] = kpos[j]; --j; }
            kpos[j + 1] = v;
        }
    }
    __syncthreads();

    for (int t = tid; t < TOK; t += 256) {
        int q = g_qid[base + t];
        int lo = bstart[q], hi = bstart[q + 1];
        int best = -1;
        for (int i = hi - 1; i >= lo; --i) {
            if (kpos[i] < t) { best = kpos[i]; break; }
        }
        g_row[base + t] = (best >= 0) ? (g_vid[base + best] + 1) : 0;
    }
}

// ---------------------------------------------------------------------------
// Embedding gather. grid = (TOK/128, NHEAD), block = 256.
// ---------------------------------------------------------------------------
__global__ __launch_bounds__(256) void gather_kernel(
    const float* __restrict__ emb, float* __restrict__ out)
{
    const int m = blockIdx.y, t0 = blockIdx.x * 128;
    const float* E = emb + (size_t)m * (KR + 1) * DDIM;
    for (int j = threadIdx.x; j < 128 * 16; j += 256) {
        int t = j >> 4, dg = j & 15;
        int row = g_row[m * TOK + t0 + t];
        float4 v;
        if (row) {
            v = *reinterpret_cast<const float4*>(E + (size_t)row * DDIM + dg * 4);
        } else {
            v = make_float4(0.f, 0.f, 0.f, 0.f);   // padding row is zero
        }
        *reinterpret_cast<float4*>(out + (size_t)(t0 + t) * CDIM + m * DDIM + dg * 4) = v;
    }
}

// ---------------------------------------------------------------------------
extern "C" void kernel_launch(void* const* d_in, const int* in_sizes, int n_in,
                              void* d_out, int out_size)
{
    (void)in_sizes; (void)n_in; (void)out_size;
    const float* x   = (const float*)d_in[0];
    const float* wq  = (const float*)d_in[1];
    const float* wk  = (const float*)d_in[2];
    const float* wv  = (const float*)d_in[3];
    const float* emb = (const float*)d_in[4];
    float* out = (float*)d_out;

    cudaFuncSetAttribute(tc_route_kernel,
                         cudaFuncAttributeMaxDynamicSharedMemorySize, SM_TOTAL);

    split_w_kernel<<<(3 * NHEAD * NTPM * 4 * 32) / 256, 256>>>(wq, wk, wv);
    bnorm_kernel<<<3 * NHEAD, 256>>>(wq, wk, wv);
    dim3 g1(TOK / CTOK, NHEAD);
    tc_route_kernel<<<g1, 256, SM_TOTAL>>>(x);
    dim3 g2(3 * NHEAD, 4);
    refine_kernel<<<g2, 256>>>(x, wq, wk, wv);
    match_kernel<<<NHEAD, 256>>>();
    dim3 g3(TOK / 128, NHEAD);
    gather_kernel<<<g3, 256>>>(emb, out);
}

// round 7
// speedup vs baseline: 3.7296x; 3.7296x over previous
#include <cuda_runtime.h>
#include <cuda_fp16.h>
#include <cstdint>

#define TOK   2048
#define CDIM  2048
#define NHEAD 32
#define DDIM  64
#define KR    1024

#define CTOK  256            // tokens per CTA (route)
#define NTPM  128            // 8-col n-tiles per matrix
#define NTT   (3 * NTPM)     // 384 n-tiles (q,k,v)
#define GSZ   16             // n-tiles per pipeline group
#define NGRP  (NTT / GSZ)    // 24
#define NT_B  1024           // bytes per n-tile (hi only)
#define GRP_B (GSZ * NT_B)   // 16 KB

#define SM_XB    (CTOK * 68 * 4)              // 69632 (x tile, pitch 68)
#define SM_NORM  (SM_XB + 2 * GRP_B)          // 102400
#define SM_TOTAL (SM_NORM + CTOK * 4)         // 103424 -> 2 CTAs/SM

// sound screening bound:  eps = EPSC * ||x_t|| * maxB + SLACK
#define EPSC  1.0254e-3f     // 1.05 * 2^-10
#define SLACK 3.0e-4f

__device__ int g_qid[NHEAD * TOK];
__device__ int g_kid[NHEAD * TOK];
__device__ int g_vid[NHEAD * TOK];
__device__ int g_row[NHEAD * TOK];
__device__ float g_maxB[3 * NHEAD];
__device__ int g_flagcnt[3 * NHEAD];
__device__ int g_flaglist[3 * NHEAD * TOK];
__device__ unsigned long long g_best[(size_t)3 * NHEAD * TOK];   // 1.5 MB
// W hi-split fp16, fragment-major: [mat][head][ntl][ks][lane][8B]
__device__ __align__(16) uint8_t g_whf[(size_t)3 * NHEAD * NTPM * NT_B];   // 12 MB

// ---------------- helpers ----------------
static __device__ __forceinline__ uint32_t s2u(const void* p) {
    uint32_t a;
    asm("{ .reg .u64 t; cvta.to.shared.u64 t, %1; cvt.u32.u64 %0, t; }"
        : "=r"(a) : "l"(p));
    return a;
}
static __device__ __forceinline__ uint32_t h2u(__half2 h) {
    uint32_t u; asm("mov.b32 %0, %1;" : "=r"(u) : "r"(*(uint32_t*)&h)); return u;
}
static __device__ __forceinline__ void mma_f16(float* d, const uint32_t* a,
                                               uint32_t b0, uint32_t b1) {
    asm volatile("mma.sync.aligned.m16n8k16.row.col.f32.f16.f16.f32 "
                 "{%0,%1,%2,%3}, {%4,%5,%6,%7}, {%8,%9}, {%0,%1,%2,%3};"
                 : "+f"(d[0]), "+f"(d[1]), "+f"(d[2]), "+f"(d[3])
                 : "r"(a[0]), "r"(a[1]), "r"(a[2]), "r"(a[3]),
                   "r"(b0), "r"(b1));
}
static __device__ __forceinline__ void cp16(uint32_t d, const void* s) {
    asm volatile("cp.async.cg.shared.global [%0], [%1], 16;"
                 :: "r"(d), "l"(s) : "memory");
}
#define CP_COMMIT() asm volatile("cp.async.commit_group;" ::: "memory")
#define CP_WAIT1()  asm volatile("cp.async.wait_group 1;" ::: "memory")
#define CP_WAIT0()  asm volatile("cp.async.wait_group 0;" ::: "memory")

// orderable packing: larger logit wins; tie -> smaller col wins
static __device__ __forceinline__ unsigned long long packcmp(float v, int col) {
    uint32_t b = __float_as_uint(v);
    uint32_t u = (b & 0x80000000u) ? ~b : (b | 0x80000000u);
    return ((unsigned long long)u << 32) | (unsigned long long)(0xFFFFFFFFu - (uint32_t)col);
}

// ---------------------------------------------------------------------------
// Prepass A: W -> fp16(hi), fragment-major.
// ---------------------------------------------------------------------------
__global__ __launch_bounds__(256) void split_w_kernel(
    const float* __restrict__ wq, const float* __restrict__ wk,
    const float* __restrict__ wv)
{
    uint32_t id = blockIdx.x * 256u + threadIdx.x;
    uint32_t lane = id & 31u;
    uint32_t ks   = (id >> 5) & 3u;
    uint32_t ntl  = (id >> 7) & 127u;
    uint32_t head = (id >> 14) & 31u;
    uint32_t mat  = id >> 19;
    const float* W = (mat == 0) ? wq : (mat == 1) ? wk : wv;
    int col = (int)(ntl * 8 + (lane >> 2));
    int k0  = (int)(ks * 16 + 2 * (lane & 3));
    size_t off = ((size_t)head * KR + col) * DDIM + k0;
    float2 v0 = *reinterpret_cast<const float2*>(W + off);
    float2 v1 = *reinterpret_cast<const float2*>(W + off + 8);
    uint2 o;
    o.x = h2u(__float22half2_rn(v0));
    o.y = h2u(__float22half2_rn(v1));
    *reinterpret_cast<uint2*>(g_whf + (size_t)id * 8) = o;
}

// ---------------------------------------------------------------------------
// Prepass B: per (mat,head) max column norm of W; zero flag counters.
// ---------------------------------------------------------------------------
__global__ __launch_bounds__(256) void bnorm_kernel(
    const float* __restrict__ wq, const float* __restrict__ wk,
    const float* __restrict__ wv)
{
    __shared__ float wmax[8];
    const int b = blockIdx.x, tid = threadIdx.x;
    const int mat = b >> 5, head = b & 31;
    if (tid == 0) g_flagcnt[b] = 0;
    const float* W = ((mat == 0) ? wq : (mat == 1) ? wk : wv)
                     + (size_t)head * KR * DDIM;
    float mx = 0.f;
    for (int col = tid; col < KR; col += 256) {
        const float4* r = reinterpret_cast<const float4*>(W + (size_t)col * DDIM);
        float s = 0.f;
        #pragma unroll
        for (int i = 0; i < 16; ++i) {
            float4 v = r[i];
            s += v.x * v.x + v.y * v.y + v.z * v.z + v.w * v.w;
        }
        mx = fmaxf(mx, s);
    }
    #pragma unroll
    for (int off = 16; off > 0; off >>= 1)
        mx = fmaxf(mx, __shfl_xor_sync(0xffffffffu, mx, off, 32));
    if ((tid & 31) == 0) wmax[tid >> 5] = mx;
    __syncthreads();
    if (tid == 0) {
        float m = wmax[0];
        #pragma unroll
        for (int w = 1; w < 8; ++w) m = fmaxf(m, wmax[w]);
        g_maxB[b] = sqrtf(m);
    }
}

// ---------------------------------------------------------------------------
// Pass 1: hh-only fp16 mma.sync with certified top-2 screening.
// grid = (8, 32), block = 256 (8 warps), 2 CTAs/SM.
// ---------------------------------------------------------------------------
__global__ __launch_bounds__(256, 2) void tc_route_kernel(const float* __restrict__ x)
{
    extern __shared__ uint8_t smem[];
    float* xs = reinterpret_cast<float*>(smem);
    float* xnorm_s = reinterpret_cast<float*>(smem + SM_NORM);
    const uint32_t sbB = s2u(smem) + SM_XB;

    const int tid = threadIdx.x, lane = tid & 31, wid = tid >> 5;
    const int m = blockIdx.y;
    const int t0 = blockIdx.x * CTOK;

    for (int i = tid; i < CTOK * 16; i += 256) {
        int t = i >> 4, c = i & 15;
        float4 v = *reinterpret_cast<const float4*>(
            x + (size_t)(t0 + t) * CDIM + m * DDIM + c * 4);
        *reinterpret_cast<float4*>(&xs[t * 68 + c * 4]) = v;
    }
    __syncthreads();

    {
        const float4* r = reinterpret_cast<const float4*>(&xs[tid * 68]);
        float s = 0.f;
        #pragma unroll
        for (int i = 0; i < 16; ++i) {
            float4 v = r[i];
            s += v.x * v.x + v.y * v.y + v.z * v.z + v.w * v.w;
        }
        xnorm_s[tid] = sqrtf(s);
    }

    uint32_t ah[2][4][4];
    const int r0 = wid * 32 + (lane >> 2);
    #pragma unroll
    for (int mt = 0; mt < 2; ++mt)
        #pragma unroll
        for (int ks = 0; ks < 4; ++ks)
            #pragma unroll
            for (int e = 0; e < 4; ++e) {
                int row = r0 + mt * 16 + (e & 1) * 8;
                int kc  = ks * 16 + 2 * (lane & 3) + (e >> 1) * 8;
                float2 v = *reinterpret_cast<const float2*>(&xs[row * 68 + kc]);
                ah[mt][ks][e] = h2u(__float22half2_rn(v));
            }
    __syncthreads();

    auto stage = [&](int g2) {
        int F0 = g2 * GSZ;
        int mat = F0 >> 7, ntl0 = F0 & (NTPM - 1);
        const uint8_t* src = g_whf
            + (((size_t)mat * NHEAD + m) * NTPM + ntl0) * NT_B + tid * 16;
        uint32_t dst = sbB + (uint32_t)(g2 & 1) * GRP_B + tid * 16;
        #pragma unroll
        for (int j = 0; j < 4; ++j)
            cp16(dst + j * 4096u, src + (size_t)j * 4096);
    };

    float max1[4], max2[4]; int bidx[4];
    #pragma unroll
    for (int s = 0; s < 4; ++s) {
        max1[s] = -3.402823466e38f; max2[s] = -3.402823466e38f; bidx[s] = 0;
    }

    stage(0); CP_COMMIT();

    #pragma unroll 1
    for (int g = 0; g < NGRP; ++g) {
        if (g + 1 < NGRP) { stage(g + 1); CP_COMMIT(); CP_WAIT1(); }
        else              { CP_WAIT0(); }
        __syncthreads();

        const uint32_t bb = sbB + (uint32_t)(g & 1) * GRP_B + (uint32_t)lane * 8u;
        #pragma unroll 1
        for (int ntg = 0; ntg < GSZ; ++ntg) {
            const int F = g * GSZ + ntg;
            float d0[4] = {0.f, 0.f, 0.f, 0.f};
            float d1[4] = {0.f, 0.f, 0.f, 0.f};
            const uint32_t tb = bb + (uint32_t)ntg * NT_B;
            #pragma unroll
            for (int ks = 0; ks < 4; ++ks) {
                uint32_t b0, b1;
                asm volatile("ld.shared.v2.b32 {%0,%1}, [%2];"
                             : "=r"(b0), "=r"(b1) : "r"(tb + ks * 256u));
                mma_f16(d0, ah[0][ks], b0, b1);
                mma_f16(d1, ah[1][ks], b0, b1);
            }
            const int cb = (F & (NTPM - 1)) * 8 + 2 * (lane & 3);
            #pragma unroll
            for (int e = 0; e < 8; ++e) {
                float v = (e < 4) ? d0[e] : d1[e - 4];
                int s = ((e >> 2) << 1) | ((e >> 1) & 1);
                int col = cb + (e & 1);
                bool gt = v > max1[s];
                max2[s] = gt ? max1[s] : fmaxf(max2[s], v);
                bidx[s] = gt ? col : bidx[s];
                max1[s] = gt ? v : max1[s];
            }

            if (((F + 1) & (NTPM - 1)) == 0) {      // matrix boundary
                const int mat = F >> 7;
                int* G = (mat == 0) ? g_qid : (mat == 1) ? g_kid : g_vid;
                const float mbv = g_maxB[mat * 32 + m];
                #pragma unroll
                for (int s = 0; s < 4; ++s) {
                    float m1 = max1[s], m2 = max2[s]; int bi = bidx[s];
                    #pragma unroll
                    for (int off = 1; off <= 2; off <<= 1) {
                        float o1 = __shfl_xor_sync(0xffffffffu, m1, off, 32);
                        float o2 = __shfl_xor_sync(0xffffffffu, m2, off, 32);
                        int   oi = __shfl_xor_sync(0xffffffffu, bi, off, 32);
                        bool bw = (o1 > m1) || (o1 == m1 && oi < bi);
                        float nm2 = bw ? fmaxf(m1, o2) : fmaxf(m2, o1);
                        m1 = bw ? o1 : m1; bi = bw ? oi : bi; m2 = nm2;
                    }
                    if ((lane & 3) == 0) {
                        int row = wid * 32 + (lane >> 2) + (s >> 1) * 16 + (s & 1) * 8;
                        G[m * TOK + t0 + row] = bi;
                        float eps = EPSC * xnorm_s[row] * mbv + SLACK;
                        if (m1 - m2 < 2.f * eps) {
                            int bslot = mat * 32 + m;
                            int p = atomicAdd(&g_flagcnt[bslot], 1);
                            g_flaglist[bslot * TOK + p] = t0 + row;
                            g_best[(size_t)bslot * TOK + t0 + row] = 0ull;
                        }
                    }
                    max1[s] = -3.402823466e38f;
                    max2[s] = -3.402823466e38f;
                    bidx[s] = 0;
                }
            }
        }
        __syncthreads();
    }
}

// ---------------------------------------------------------------------------
// Pass 2a: exact fp32 partial argmax for flagged tokens.
// grid = (96, 8): bucket b x col-chunk cc (128 cols). W chunk loaded ONCE into
// smem; x slices live in registers; w reads are warp-uniform broadcasts.
// Cross-chunk combine via atomicMax on packed u64.
// ---------------------------------------------------------------------------
__global__ __launch_bounds__(256) void refine_kernel(
    const float* __restrict__ x, const float* __restrict__ wq,
    const float* __restrict__ wk, const float* __restrict__ wv)
{
    __shared__ float4 wsm[128 * 16];   // 32 KB: [col][k4]

    const int b = blockIdx.x, cc = blockIdx.y;
    const int cnt = g_flagcnt[b];
    if (cnt == 0) return;
    const int mat = b >> 5, head = b & 31;
    const int tid = threadIdx.x, lane = tid & 31, wid = tid >> 5;

    const float* W = ((mat == 0) ? wq : (mat == 1) ? wk : wv)
                     + ((size_t)head * KR + cc * 128) * DDIM;
    for (int i = tid; i < 128 * 16; i += 256)
        wsm[i] = reinterpret_cast<const float4*>(W)[i];
    __syncthreads();

    const int* list = g_flaglist + b * TOK;
    for (int base = 0; base < cnt; base += 32) {
        int ti = base + lane;
        bool valid = ti < cnt;
        int token = list[valid ? ti : 0];
        float4 xr[16];
        const float4* xp = reinterpret_cast<const float4*>(
            x + (size_t)token * CDIM + head * DDIM);
        #pragma unroll
        for (int i = 0; i < 16; ++i) xr[i] = xp[i];

        float best = -3.402823466e38f;
        int bcol = 0;
        #pragma unroll 4
        for (int j = 0; j < 16; ++j) {
            const float4* wr = &wsm[(wid * 16 + j) * 16];
            float acc = 0.f;
            #pragma unroll
            for (int kk = 0; kk < 16; ++kk) {
                float4 w4 = wr[kk];
                acc = fmaf(xr[kk].x, w4.x, acc);
                acc = fmaf(xr[kk].y, w4.y, acc);
                acc = fmaf(xr[kk].z, w4.z, acc);
                acc = fmaf(xr[kk].w, w4.w, acc);
            }
            if (acc > best) { best = acc; bcol = cc * 128 + wid * 16 + j; }
        }
        if (valid)
            atomicMax(&g_best[(size_t)b * TOK + token], packcmp(best, bcol));
    }
}

// ---------------------------------------------------------------------------
// Pass 2b: commit refined argmaxes. grid = 96.
// ---------------------------------------------------------------------------
__global__ __launch_bounds__(256) void commit_kernel()
{
    const int b = blockIdx.x;
    const int cnt = g_flagcnt[b];
    const int mat = b >> 5, head = b & 31;
    int* G = (mat == 0) ? g_qid : (mat == 1) ? g_kid : g_vid;
    const int* list = g_flaglist + b * TOK;
    for (int i = threadIdx.x; i < cnt; i += 256) {
        int token = list[i];
        unsigned long long p = g_best[(size_t)b * TOK + token];
        G[head * TOK + token] = (int)(0xFFFFFFFFu - (uint32_t)(p & 0xFFFFFFFFull));
    }
}

// ---------------------------------------------------------------------------
// tau matching via bucketed counting sort. grid=NHEAD, block=256.
// ---------------------------------------------------------------------------
__global__ __launch_bounds__(256) void match_kernel()
{
    __shared__ int cnt[KR];
    __shared__ int bstart[KR + 1];
    __shared__ int kpos[TOK];
    __shared__ int wsum[8];

    const int m = blockIdx.x, tid = threadIdx.x;
    const int lane = tid & 31, wid = tid >> 5;
    const int base = m * TOK;

    for (int i = tid; i < KR; i += 256) cnt[i] = 0;
    __syncthreads();
    for (int t = tid; t < TOK; t += 256) atomicAdd(&cnt[g_kid[base + t]], 1);
    __syncthreads();

    int c0 = cnt[tid * 4], c1 = cnt[tid * 4 + 1],
        c2 = cnt[tid * 4 + 2], c3 = cnt[tid * 4 + 3];
    int tot = c0 + c1 + c2 + c3;
    int incl = tot;
    #pragma unroll
    for (int off = 1; off < 32; off <<= 1) {
        int nv = __shfl_up_sync(0xffffffffu, incl, off, 32);
        if (lane >= off) incl += nv;
    }
    if (lane == 31) wsum[wid] = incl;
    __syncthreads();
    if (tid == 0) {
        int r = 0;
        #pragma unroll
        for (int w = 0; w < 8; ++w) { int v = wsum[w]; wsum[w] = r; r += v; }
    }
    __syncthreads();
    int ex = incl - tot + wsum[wid];
    bstart[tid * 4]     = ex;
    bstart[tid * 4 + 1] = ex + c0;
    bstart[tid * 4 + 2] = ex + c0 + c1;
    bstart[tid * 4 + 3] = ex + c0 + c1 + c2;
    if (tid == 0) bstart[KR] = TOK;
    __syncthreads();
    cnt[tid * 4]     = ex;
    cnt[tid * 4 + 1] = ex + c0;
    cnt[tid * 4 + 2] = ex + c0 + c1;
    cnt[tid * 4 + 3] = ex + c0 + c1 + c2;
    __syncthreads();

    for (int t = tid; t < TOK; t += 256) {
        int k = g_kid[base + t];
        int p = atomicAdd(&cnt[k], 1);
        kpos[p] = t;
    }
    __syncthreads();

    for (int b = tid; b < KR; b += 256) {
        int lo = bstart[b], hi = bstart[b + 1];
        for (int i = lo + 1; i < hi; ++i) {
            int v = kpos[i], j = i - 1;
            while (j >= lo && kpos[j] > v) { kpos[j + 1] = kpos[j]; --j; }
            kpos[j + 1] = v;
        }
    }
    __syncthreads();

    for (int t = tid; t < TOK; t += 256) {
        int q = g_qid[base + t];
        int lo = bstart[q], hi = bstart[q + 1];
        int best = -1;
        for (int i = hi - 1; i >= lo; --i) {
            if (kpos[i] < t) { best = kpos[i]; break; }
        }
        g_row[base + t] = (best >= 0) ? (g_vid[base + best] + 1) : 0;
    }
}

// ---------------------------------------------------------------------------
// Embedding gather. grid = (TOK/128, NHEAD), block = 256.
// ---------------------------------------------------------------------------
__global__ __launch_bounds__(256) void gather_kernel(
    const float* __restrict__ emb, float* __restrict__ out)
{
    const int m = blockIdx.y, t0 = blockIdx.x * 128;
    const float* E = emb + (size_t)m * (KR + 1) * DDIM;
    for (int j = threadIdx.x; j < 128 * 16; j += 256) {
        int t = j >> 4, dg = j & 15;
        int row = g_row[m * TOK + t0 + t];
        float4 v;
        if (row) {
            v = *reinterpret_cast<const float4*>(E + (size_t)row * DDIM + dg * 4);
        } else {
            v = make_float4(0.f, 0.f, 0.f, 0.f);
        }
        *reinterpret_cast<float4*>(out + (size_t)(t0 + t) * CDIM + m * DDIM + dg * 4) = v;
    }
}

// ---------------------------------------------------------------------------
extern "C" void kernel_launch(void* const* d_in, const int* in_sizes, int n_in,
                              void* d_out, int out_size)
{
    (void)in_sizes; (void)n_in; (void)out_size;
    const float* x   = (const float*)d_in[0];
    const float* wq  = (const float*)d_in[1];
    const float* wk  = (const float*)d_in[2];
    const float* wv  = (const float*)d_in[3];
    const float* emb = (const float*)d_in[4];
    float* out = (float*)d_out;

    cudaFuncSetAttribute(tc_route_kernel,
                         cudaFuncAttributeMaxDynamicSharedMemorySize, SM_TOTAL);

    split_w_kernel<<<(3 * NHEAD * NTPM * 4 * 32) / 256, 256>>>(wq, wk, wv);
    bnorm_kernel<<<3 * NHEAD, 256>>>(wq, wk, wv);
    dim3 g1(TOK / CTOK, NHEAD);
    tc_route_kernel<<<g1, 256, SM_TOTAL>>>(x);
    dim3 g2(3 * NHEAD, 8);
    refine_kernel<<<g2, 256>>>(x, wq, wk, wv);
    commit_kernel<<<3 * NHEAD, 256>>>();
    match_kernel<<<NHEAD, 256>>>();
    dim3 g3(TOK / 128, NHEAD);
    gather_kernel<<<g3, 256>>>(emb, out);
}

// round 8
// speedup vs baseline: 6.9352x; 1.8595x over previous
#include <cuda_runtime.h>
#include <cuda_fp16.h>
#include <cstdint>

#define TOK   2048
#define CDIM  2048
#define NHEAD 32
#define DDIM  64
#define KR    1024

#define CTOK  256            // tokens per CTA
#define NTPM  128            // 8-col n-tiles per matrix
#define NTT   (3 * NTPM)     // 384 n-tiles (q,k,v)
#define GSZ   8              // n-tiles per pipeline group
#define NGRP  (NTT / GSZ)    // 48
#define NT_B  2048           // bytes per n-tile: 4 ks x 2 splits x 32 lanes x 8B
#define GRP_B (GSZ * NT_B)   // 16 KB

#define SM_XPIT 68
#define SM_B    (CTOK * SM_XPIT * 4)          // 69632
#define SM_TOTAL (SM_B + 2 * GRP_B)           // 102400 -> 2 CTAs/SM

__device__ int g_qid[NHEAD * TOK];
__device__ int g_kid[NHEAD * TOK];
__device__ int g_vid[NHEAD * TOK];
__device__ int g_row[NHEAD * TOK];
// W pre-split to fp16 hi/lo, fragment-major: [mat][head][ntl][ks][s][lane][b0b1]
__device__ __align__(16) uint8_t g_whf[(size_t)3 * NHEAD * NTPM * NT_B];   // 24 MB

// ---------------- helpers ----------------
static __device__ __forceinline__ uint32_t s2u(const void* p) {
    uint32_t a;
    asm("{ .reg .u64 t; cvta.to.shared.u64 t, %1; cvt.u32.u64 %0, t; }"
        : "=r"(a) : "l"(p));
    return a;
}
static __device__ __forceinline__ uint32_t h2u(__half2 h) {
    uint32_t u; asm("mov.b32 %0, %1;" : "=r"(u) : "r"(*(uint32_t*)&h)); return u;
}
static __device__ __forceinline__ void mma_f16(float* d, const uint32_t* a,
                                               uint32_t b0, uint32_t b1) {
    asm volatile("mma.sync.aligned.m16n8k16.row.col.f32.f16.f16.f32 "
                 "{%0,%1,%2,%3}, {%4,%5,%6,%7}, {%8,%9}, {%0,%1,%2,%3};"
                 : "+f"(d[0]), "+f"(d[1]), "+f"(d[2]), "+f"(d[3])
                 : "r"(a[0]), "r"(a[1]), "r"(a[2]), "r"(a[3]),
                   "r"(b0), "r"(b1));
}
static __device__ __forceinline__ void cp16(uint32_t d, const void* s) {
    asm volatile("cp.async.cg.shared.global [%0], [%1], 16;"
                 :: "r"(d), "l"(s) : "memory");
}
#define CP_COMMIT() asm volatile("cp.async.commit_group;" ::: "memory")
#define CP_WAIT1()  asm volatile("cp.async.wait_group 1;" ::: "memory")
#define CP_WAIT0()  asm volatile("cp.async.wait_group 0;" ::: "memory")

// split one float pair into packed fp16 hi / lo
static __device__ __forceinline__ void split2(float2 v, uint32_t& h, uint32_t& l) {
    __half2 hh = __float22half2_rn(v);
    float2 hf = __half22float2(hh);
    __half2 ll = __float22half2_rn(make_float2(v.x - hf.x, v.y - hf.y));
    h = h2u(hh); l = h2u(ll);
}

// ---------------------------------------------------------------------------
// Prepass: split W into fp16 hi/lo, fragment-major.
// id bits: lane[0:5) s[5] ks[6:8) ntl[8:15) head[15:20) mat[20:22)
// ---------------------------------------------------------------------------
__global__ __launch_bounds__(256) void split_w_kernel(
    const float* __restrict__ wq, const float* __restrict__ wk,
    const float* __restrict__ wv)
{
    uint32_t id = blockIdx.x * 256u + threadIdx.x;
    uint32_t lane = id & 31u;
    uint32_t s    = (id >> 5) & 1u;
    uint32_t ks   = (id >> 6) & 3u;
    uint32_t ntl  = (id >> 8) & 127u;
    uint32_t head = (id >> 15) & 31u;
    uint32_t mat  = id >> 20;
    const float* W = (mat == 0) ? wq : (mat == 1) ? wk : wv;
    int col = (int)(ntl * 8 + (lane >> 2));
    int k0  = (int)(ks * 16 + 2 * (lane & 3));
    size_t off = ((size_t)head * KR + col) * DDIM + k0;
    float2 v0 = *reinterpret_cast<const float2*>(W + off);
    float2 v1 = *reinterpret_cast<const float2*>(W + off + 8);
    uint32_t h0, l0, h1, l1;
    split2(v0, h0, l0);
    split2(v1, h1, l1);
    uint2 o;
    if (s == 0) { o.x = h0; o.y = h1; } else { o.x = l0; o.y = l1; }
    *reinterpret_cast<uint2*>(g_whf + (size_t)id * 8) = o;
}

// ---------------------------------------------------------------------------
// Route kernel: 2-split fp16 mma.sync argmax-GEMM, de-chained accumulators.
// grid = (8, 32), block = 256 (8 warps x 32 tokens), 2 CTAs/SM.
// ---------------------------------------------------------------------------
__global__ __launch_bounds__(256, 2) void tc_route_kernel(const float* __restrict__ x)
{
    extern __shared__ uint8_t smem[];
    float* xs = reinterpret_cast<float*>(smem);
    const uint32_t sbB = s2u(smem) + SM_B;

    const int tid = threadIdx.x, lane = tid & 31, wid = tid >> 5;
    const int m = blockIdx.y;
    const int t0 = blockIdx.x * CTOK;

    // stage x tile [CTOK][64] (pitch 68)
    for (int i = tid; i < CTOK * 16; i += 256) {
        int t = i >> 4, c = i & 15;
        float4 v = *reinterpret_cast<const float4*>(
            x + (size_t)(t0 + t) * CDIM + m * DDIM + c * 4);
        *reinterpret_cast<float4*>(&xs[t * SM_XPIT + c * 4]) = v;
    }
    __syncthreads();

    // A fragments (fp16 hi/lo): 2 m-tiles x 4 ksteps x 4 regs, packed half2
    uint32_t ah[2][4][4], al[2][4][4];
    const int r0 = wid * 32 + (lane >> 2);
    #pragma unroll
    for (int mt = 0; mt < 2; ++mt)
        #pragma unroll
        for (int ks = 0; ks < 4; ++ks)
            #pragma unroll
            for (int e = 0; e < 4; ++e) {
                int row = r0 + mt * 16 + (e & 1) * 8;
                int kc  = ks * 16 + 2 * (lane & 3) + (e >> 1) * 8;
                float2 v = *reinterpret_cast<const float2*>(&xs[row * SM_XPIT + kc]);
                split2(v, ah[mt][ks][e], al[mt][ks][e]);
            }

    auto stage = [&](int g2) {
        int F0 = g2 * GSZ;
        int mat = F0 >> 7, ntl0 = F0 & (NTPM - 1);
        const uint8_t* src = g_whf
            + (((size_t)mat * NHEAD + m) * NTPM + ntl0) * NT_B + tid * 16;
        uint32_t dst = sbB + (uint32_t)(g2 & 1) * GRP_B + tid * 16;
        #pragma unroll
        for (int j = 0; j < 4; ++j)
            cp16(dst + j * 4096u, src + (size_t)j * 4096);
    };

    float bmax[4]; int bidx[4];
    #pragma unroll
    for (int sl = 0; sl < 4; ++sl) { bmax[sl] = -3.402823466e38f; bidx[sl] = 0; }

    stage(0); CP_COMMIT();

    #pragma unroll 1
    for (int g = 0; g < NGRP; ++g) {
        if (g + 1 < NGRP) { stage(g + 1); CP_COMMIT(); CP_WAIT1(); }
        else              { CP_WAIT0(); }
        __syncthreads();

        const uint32_t bb = sbB + (uint32_t)(g & 1) * GRP_B + (uint32_t)lane * 8u;
        #pragma unroll 1
        for (int ntg = 0; ntg < GSZ; ++ntg) {
            const int F = g * GSZ + ntg;
            const uint32_t tb = bb + (uint32_t)ntg * NT_B;

            // preload all B fragments for this n-tile (8 x LDS.64)
            uint32_t bh[4][2], bl[4][2];
            #pragma unroll
            for (int ks = 0; ks < 4; ++ks) {
                asm volatile("ld.shared.v2.b32 {%0,%1}, [%2];"
                             : "=r"(bh[ks][0]), "=r"(bh[ks][1])
                             : "r"(tb + ks * 512u));
                asm volatile("ld.shared.v2.b32 {%0,%1}, [%2];"
                             : "=r"(bl[ks][0]), "=r"(bl[ks][1])
                             : "r"(tb + ks * 512u + 256u));
            }

            // 6 independent accumulator chains, depth 4 each
            float dhh0[4] = {0.f, 0.f, 0.f, 0.f}, dlh0[4] = {0.f, 0.f, 0.f, 0.f},
                  dhl0[4] = {0.f, 0.f, 0.f, 0.f}, dhh1[4] = {0.f, 0.f, 0.f, 0.f},
                  dlh1[4] = {0.f, 0.f, 0.f, 0.f}, dhl1[4] = {0.f, 0.f, 0.f, 0.f};
            #pragma unroll
            for (int ks = 0; ks < 4; ++ks) {
                mma_f16(dhh0, ah[0][ks], bh[ks][0], bh[ks][1]);
                mma_f16(dhh1, ah[1][ks], bh[ks][0], bh[ks][1]);
                mma_f16(dlh0, al[0][ks], bh[ks][0], bh[ks][1]);
                mma_f16(dlh1, al[1][ks], bh[ks][0], bh[ks][1]);
                mma_f16(dhl0, ah[0][ks], bl[ks][0], bl[ks][1]);
                mma_f16(dhl1, ah[1][ks], bl[ks][0], bl[ks][1]);
            }
            float d0[4], d1[4];
            #pragma unroll
            for (int e = 0; e < 4; ++e) {
                d0[e] = (dhh0[e] + dlh0[e]) + dhl0[e];
                d1[e] = (dhh1[e] + dlh1[e]) + dhl1[e];
            }

            // running per-token argmax; cols ascend -> strict '>' keeps first
            const int cb = (F & (NTPM - 1)) * 8 + 2 * (lane & 3);
            if (d0[0] > bmax[0]) { bmax[0] = d0[0]; bidx[0] = cb; }
            if (d0[1] > bmax[0]) { bmax[0] = d0[1]; bidx[0] = cb + 1; }
            if (d0[2] > bmax[1]) { bmax[1] = d0[2]; bidx[1] = cb; }
            if (d0[3] > bmax[1]) { bmax[1] = d0[3]; bidx[1] = cb + 1; }
            if (d1[0] > bmax[2]) { bmax[2] = d1[0]; bidx[2] = cb; }
            if (d1[1] > bmax[2]) { bmax[2] = d1[1]; bidx[2] = cb + 1; }
            if (d1[2] > bmax[3]) { bmax[3] = d1[2]; bidx[3] = cb; }
            if (d1[3] > bmax[3]) { bmax[3] = d1[3]; bidx[3] = cb + 1; }

            if (((F + 1) & (NTPM - 1)) == 0) {      // matrix boundary
                const int mat = F >> 7;
                int* G = (mat == 0) ? g_qid : (mat == 1) ? g_kid : g_vid;
                #pragma unroll
                for (int sl = 0; sl < 4; ++sl) {
                    float bv = bmax[sl]; int bi = bidx[sl];
                    #pragma unroll
                    for (int off = 1; off < 4; off <<= 1) {
                        float om = __shfl_xor_sync(0xffffffffu, bv, off, 32);
                        int   oi = __shfl_xor_sync(0xffffffffu, bi, off, 32);
                        if (om > bv || (om == bv && oi < bi)) { bv = om; bi = oi; }
                    }
                    if ((lane & 3) == 0)
                        G[m * TOK + t0 + wid * 32 + (sl >> 1) * 16
                          + (lane >> 2) + (sl & 1) * 8] = bi;
                    bmax[sl] = -3.402823466e38f; bidx[sl] = 0;
                }
            }
        }
        __syncthreads();
    }
}

// ---------------------------------------------------------------------------
// tau matching via bucketed counting sort. grid=NHEAD, block=256.
// ---------------------------------------------------------------------------
__global__ __launch_bounds__(256) void match_kernel()
{
    __shared__ int cnt[KR];
    __shared__ int bstart[KR + 1];
    __shared__ int kpos[TOK];
    __shared__ int wsum[8];

    const int m = blockIdx.x, tid = threadIdx.x;
    const int lane = tid & 31, wid = tid >> 5;
    const int base = m * TOK;

    for (int i = tid; i < KR; i += 256) cnt[i] = 0;
    __syncthreads();
    for (int t = tid; t < TOK; t += 256) atomicAdd(&cnt[g_kid[base + t]], 1);
    __syncthreads();

    int c0 = cnt[tid * 4], c1 = cnt[tid * 4 + 1],
        c2 = cnt[tid * 4 + 2], c3 = cnt[tid * 4 + 3];
    int tot = c0 + c1 + c2 + c3;
    int incl = tot;
    #pragma unroll
    for (int off = 1; off < 32; off <<= 1) {
        int nv = __shfl_up_sync(0xffffffffu, incl, off, 32);
        if (lane >= off) incl += nv;
    }
    if (lane == 31) wsum[wid] = incl;
    __syncthreads();
    if (tid == 0) {
        int r = 0;
        #pragma unroll
        for (int w = 0; w < 8; ++w) { int v = wsum[w]; wsum[w] = r; r += v; }
    }
    __syncthreads();
    int ex = incl - tot + wsum[wid];
    bstart[tid * 4]     = ex;
    bstart[tid * 4 + 1] = ex + c0;
    bstart[tid * 4 + 2] = ex + c0 + c1;
    bstart[tid * 4 + 3] = ex + c0 + c1 + c2;
    if (tid == 0) bstart[KR] = TOK;
    __syncthreads();
    cnt[tid * 4]     = ex;
    cnt[tid * 4 + 1] = ex + c0;
    cnt[tid * 4 + 2] = ex + c0 + c1;
    cnt[tid * 4 + 3] = ex + c0 + c1 + c2;
    __syncthreads();

    for (int t = tid; t < TOK; t += 256) {
        int k = g_kid[base + t];
        int p = atomicAdd(&cnt[k], 1);
        kpos[p] = t;
    }
    __syncthreads();

    for (int b = tid; b < KR; b += 256) {
        int lo = bstart[b], hi = bstart[b + 1];
        for (int i = lo + 1; i < hi; ++i) {
            int v = kpos[i], j = i - 1;
            while (j >= lo && kpos[j] > v) { kpos[j + 1] = kpos[j]; --j; }
            kpos[j + 1] = v;
        }
    }
    __syncthreads();

    for (int t = tid; t < TOK; t += 256) {
        int q = g_qid[base + t];
        int lo = bstart[q], hi = bstart[q + 1];
        int best = -1;
        for (int i = hi - 1; i >= lo; --i) {
            if (kpos[i] < t) { best = kpos[i]; break; }
        }
        g_row[base + t] = (best >= 0) ? (g_vid[base + best] + 1) : 0;
    }
}

// ---------------------------------------------------------------------------
// Embedding gather. grid = (TOK/128, NHEAD), block = 256.
// ---------------------------------------------------------------------------
__global__ __launch_bounds__(256) void gather_kernel(
    const float* __restrict__ emb, float* __restrict__ out)
{
    const int m = blockIdx.y, t0 = blockIdx.x * 128;
    const float* E = emb + (size_t)m * (KR + 1) * DDIM;
    for (int j = threadIdx.x; j < 128 * 16; j += 256) {
        int t = j >> 4, dg = j & 15;
        int row = g_row[m * TOK + t0 + t];
        float4 v;
        if (row) {
            v = *reinterpret_cast<const float4*>(E + (size_t)row * DDIM + dg * 4);
        } else {
            v = make_float4(0.f, 0.f, 0.f, 0.f);   // padding row is zero
        }
        *reinterpret_cast<float4*>(out + (size_t)(t0 + t) * CDIM + m * DDIM + dg * 4) = v;
    }
}

// ---------------------------------------------------------------------------
extern "C" void kernel_launch(void* const* d_in, const int* in_sizes, int n_in,
                              void* d_out, int out_size)
{
    (void)in_sizes; (void)n_in; (void)out_size;
    const float* x   = (const float*)d_in[0];
    const float* wq  = (const float*)d_in[1];
    const float* wk  = (const float*)d_in[2];
    const float* wv  = (const float*)d_in[3];
    const float* emb = (const float*)d_in[4];
    float* out = (float*)d_out;

    cudaFuncSetAttribute(tc_route_kernel,
                         cudaFuncAttributeMaxDynamicSharedMemorySize, SM_TOTAL);

    split_w_kernel<<<(3u << 20) / 256, 256>>>(wq, wk, wv);
    dim3 g1(TOK / CTOK, NHEAD);
    tc_route_kernel<<<g1, 256, SM_TOTAL>>>(x);
    match_kernel<<<NHEAD, 256>>>();
    dim3 g3(TOK / 128, NHEAD);
    gather_kernel<<<g3, 256>>>(emb, out);
}

// round 9
// speedup vs baseline: 7.6064x; 1.0968x over previous
#include <cuda_runtime.h>
#include <cuda_fp16.h>
#include <cstdint>

#define TOK   2048
#define CDIM  2048
#define NHEAD 32
#define DDIM  64
#define KR    1024

#define CTOK  256            // tokens per CTA
#define NTPM  128            // 8-col n-tiles per matrix
#define NTT   (3 * NTPM)     // 384 n-tiles (q,k,v)
#define GSZ   8              // n-tiles per pipeline group
#define NGRP  (NTT / GSZ)    // 48
#define NT_B  2048           // bytes per n-tile: 4 ks x 32 lanes x 16B (hi+lo interleaved)
#define GRP_B (GSZ * NT_B)   // 16 KB

#define SM_XPIT 68
#define SM_B    (CTOK * SM_XPIT * 4)          // 69632
#define SM_TOTAL (SM_B + 2 * GRP_B)           // 102400 -> 2 CTAs/SM

__device__ int g_qid[NHEAD * TOK];
__device__ int g_kid[NHEAD * TOK];
__device__ int g_vid[NHEAD * TOK];
__device__ int g_row[NHEAD * TOK];
// W fp16 hi/lo interleaved, fragment-major: [mat][head][ntl][ks][lane]{h0,h1,l0,l1}
__device__ __align__(16) uint8_t g_whf[(size_t)3 * NHEAD * NTPM * NT_B];   // 24 MB

// ---------------- helpers ----------------
static __device__ __forceinline__ uint32_t s2u(const void* p) {
    uint32_t a;
    asm("{ .reg .u64 t; cvta.to.shared.u64 t, %1; cvt.u32.u64 %0, t; }"
        : "=r"(a) : "l"(p));
    return a;
}
static __device__ __forceinline__ uint32_t h2u(__half2 h) {
    uint32_t u; asm("mov.b32 %0, %1;" : "=r"(u) : "r"(*(uint32_t*)&h)); return u;
}
static __device__ __forceinline__ void mma_f16(float* d, const uint32_t* a,
                                               uint32_t b0, uint32_t b1) {
    asm volatile("mma.sync.aligned.m16n8k16.row.col.f32.f16.f16.f32 "
                 "{%0,%1,%2,%3}, {%4,%5,%6,%7}, {%8,%9}, {%0,%1,%2,%3};"
                 : "+f"(d[0]), "+f"(d[1]), "+f"(d[2]), "+f"(d[3])
                 : "r"(a[0]), "r"(a[1]), "r"(a[2]), "r"(a[3]),
                   "r"(b0), "r"(b1));
}
static __device__ __forceinline__ void cp16(uint32_t d, const void* s) {
    asm volatile("cp.async.cg.shared.global [%0], [%1], 16;"
                 :: "r"(d), "l"(s) : "memory");
}
#define CP_COMMIT() asm volatile("cp.async.commit_group;" ::: "memory")
#define CP_WAIT1()  asm volatile("cp.async.wait_group 1;" ::: "memory")
#define CP_WAIT0()  asm volatile("cp.async.wait_group 0;" ::: "memory")

// split one float pair into packed fp16 hi / lo
static __device__ __forceinline__ void split2(float2 v, uint32_t& h, uint32_t& l) {
    __half2 hh = __float22half2_rn(v);
    float2 hf = __half22float2(hh);
    __half2 ll = __float22half2_rn(make_float2(v.x - hf.x, v.y - hf.y));
    h = h2u(hh); l = h2u(ll);
}

// ---------------------------------------------------------------------------
// Prepass: split W into fp16 hi/lo, fragment-major, hi/lo interleaved 16B.
// id bits: lane[0:5) ks[5:7) ntl[7:14) head[14:19) mat[19:21)
// ---------------------------------------------------------------------------
__global__ __launch_bounds__(256) void split_w_kernel(
    const float* __restrict__ wq, const float* __restrict__ wk,
    const float* __restrict__ wv)
{
    uint32_t id = blockIdx.x * 256u + threadIdx.x;
    uint32_t lane = id & 31u;
    uint32_t ks   = (id >> 5) & 3u;
    uint32_t ntl  = (id >> 7) & 127u;
    uint32_t head = (id >> 14) & 31u;
    uint32_t mat  = id >> 19;
    const float* W = (mat == 0) ? wq : (mat == 1) ? wk : wv;
    int col = (int)(ntl * 8 + (lane >> 2));
    int k0  = (int)(ks * 16 + 2 * (lane & 3));
    size_t off = ((size_t)head * KR + col) * DDIM + k0;
    float2 v0 = *reinterpret_cast<const float2*>(W + off);
    float2 v1 = *reinterpret_cast<const float2*>(W + off + 8);
    uint32_t h0, l0, h1, l1;
    split2(v0, h0, l0);
    split2(v1, h1, l1);
    uint4 o; o.x = h0; o.y = h1; o.z = l0; o.w = l1;
    *reinterpret_cast<uint4*>(g_whf + (size_t)id * 16) = o;
}

// ---------------------------------------------------------------------------
// Route kernel: 2-split fp16 mma.sync argmax-GEMM.
// grid = (8, 32), block = 256 (8 warps x 32 tokens), 2 CTAs/SM.
// ---------------------------------------------------------------------------
__global__ __launch_bounds__(256, 2) void tc_route_kernel(const float* __restrict__ x)
{
    extern __shared__ uint8_t smem[];
    float* xs = reinterpret_cast<float*>(smem);
    const uint32_t sbB = s2u(smem) + SM_B;

    const int tid = threadIdx.x, lane = tid & 31, wid = tid >> 5;
    const int m = blockIdx.y;
    const int t0 = blockIdx.x * CTOK;

    // stage x tile [CTOK][64] (pitch 68)
    for (int i = tid; i < CTOK * 16; i += 256) {
        int t = i >> 4, c = i & 15;
        float4 v = *reinterpret_cast<const float4*>(
            x + (size_t)(t0 + t) * CDIM + m * DDIM + c * 4);
        *reinterpret_cast<float4*>(&xs[t * SM_XPIT + c * 4]) = v;
    }
    __syncthreads();

    // A fragments (fp16 hi/lo): 2 m-tiles x 4 ksteps x 4 regs, packed half2
    uint32_t ah[2][4][4], al[2][4][4];
    const int r0 = wid * 32 + (lane >> 2);
    #pragma unroll
    for (int mt = 0; mt < 2; ++mt)
        #pragma unroll
        for (int ks = 0; ks < 4; ++ks)
            #pragma unroll
            for (int e = 0; e < 4; ++e) {
                int row = r0 + mt * 16 + (e & 1) * 8;
                int kc  = ks * 16 + 2 * (lane & 3) + (e >> 1) * 8;
                float2 v = *reinterpret_cast<const float2*>(&xs[row * SM_XPIT + kc]);
                split2(v, ah[mt][ks][e], al[mt][ks][e]);
            }

    auto stage = [&](int g2) {
        int F0 = g2 * GSZ;
        int mat = F0 >> 7, ntl0 = F0 & (NTPM - 1);
        const uint8_t* src = g_whf
            + (((size_t)mat * NHEAD + m) * NTPM + ntl0) * NT_B + tid * 16;
        uint32_t dst = sbB + (uint32_t)(g2 & 1) * GRP_B + tid * 16;
        #pragma unroll
        for (int j = 0; j < 4; ++j)
            cp16(dst + j * 4096u, src + (size_t)j * 4096);
    };

    float bmax[4]; int bidx[4];
    #pragma unroll
    for (int sl = 0; sl < 4; ++sl) { bmax[sl] = -3.402823466e38f; bidx[sl] = 0; }

    stage(0); CP_COMMIT();

    #pragma unroll 1
    for (int g = 0; g < NGRP; ++g) {
        if (g + 1 < NGRP) { stage(g + 1); CP_COMMIT(); CP_WAIT1(); }
        else              { CP_WAIT0(); }
        __syncthreads();

        const uint32_t bb = sbB + (uint32_t)(g & 1) * GRP_B + (uint32_t)lane * 16u;
        #pragma unroll 2
        for (int ntg = 0; ntg < GSZ; ++ntg) {
            const int F = g * GSZ + ntg;
            float d0[4] = {0.f, 0.f, 0.f, 0.f};
            float d1[4] = {0.f, 0.f, 0.f, 0.f};
            const uint32_t tb = bb + (uint32_t)ntg * NT_B;
            #pragma unroll
            for (int ks = 0; ks < 4; ++ks) {
                uint32_t bh0, bh1, bl0, bl1;
                asm volatile("ld.shared.v4.b32 {%0,%1,%2,%3}, [%4];"
                             : "=r"(bh0), "=r"(bh1), "=r"(bl0), "=r"(bl1)
                             : "r"(tb + ks * 512u));
                mma_f16(d0, ah[0][ks], bh0, bh1);   // hh
                mma_f16(d0, al[0][ks], bh0, bh1);   // lh
                mma_f16(d0, ah[0][ks], bl0, bl1);   // hl
                mma_f16(d1, ah[1][ks], bh0, bh1);
                mma_f16(d1, al[1][ks], bh0, bh1);
                mma_f16(d1, ah[1][ks], bl0, bl1);
            }
            // running per-token argmax; cols ascend -> strict '>' keeps first
            const int cb = (F & (NTPM - 1)) * 8 + 2 * (lane & 3);
            if (d0[0] > bmax[0]) { bmax[0] = d0[0]; bidx[0] = cb; }
            if (d0[1] > bmax[0]) { bmax[0] = d0[1]; bidx[0] = cb + 1; }
            if (d0[2] > bmax[1]) { bmax[1] = d0[2]; bidx[1] = cb; }
            if (d0[3] > bmax[1]) { bmax[1] = d0[3]; bidx[1] = cb + 1; }
            if (d1[0] > bmax[2]) { bmax[2] = d1[0]; bidx[2] = cb; }
            if (d1[1] > bmax[2]) { bmax[2] = d1[1]; bidx[2] = cb + 1; }
            if (d1[2] > bmax[3]) { bmax[3] = d1[2]; bidx[3] = cb; }
            if (d1[3] > bmax[3]) { bmax[3] = d1[3]; bidx[3] = cb + 1; }

            if (((F + 1) & (NTPM - 1)) == 0) {      // matrix boundary
                const int mat = F >> 7;
                int* G = (mat == 0) ? g_qid : (mat == 1) ? g_kid : g_vid;
                #pragma unroll
                for (int sl = 0; sl < 4; ++sl) {
                    float bv = bmax[sl]; int bi = bidx[sl];
                    #pragma unroll
                    for (int off = 1; off < 4; off <<= 1) {
                        float om = __shfl_xor_sync(0xffffffffu, bv, off, 32);
                        int   oi = __shfl_xor_sync(0xffffffffu, bi, off, 32);
                        if (om > bv || (om == bv && oi < bi)) { bv = om; bi = oi; }
                    }
                    if ((lane & 3) == 0)
                        G[m * TOK + t0 + wid * 32 + (sl >> 1) * 16
                          + (lane >> 2) + (sl & 1) * 8] = bi;
                    bmax[sl] = -3.402823466e38f; bidx[sl] = 0;
                }
            }
        }
        __syncthreads();
    }
}

// ---------------------------------------------------------------------------
// tau matching via bucketed counting sort. grid=NHEAD, block=256.
// ---------------------------------------------------------------------------
__global__ __launch_bounds__(256) void match_kernel()
{
    __shared__ int cnt[KR];
    __shared__ int bstart[KR + 1];
    __shared__ int kpos[TOK];
    __shared__ int wsum[8];

    const int m = blockIdx.x, tid = threadIdx.x;
    const int lane = tid & 31, wid = tid >> 5;
    const int base = m * TOK;

    for (int i = tid; i < KR; i += 256) cnt[i] = 0;
    __syncthreads();
    for (int t = tid; t < TOK; t += 256) atomicAdd(&cnt[g_kid[base + t]], 1);
    __syncthreads();

    int c0 = cnt[tid * 4], c1 = cnt[tid * 4 + 1],
        c2 = cnt[tid * 4 + 2], c3 = cnt[tid * 4 + 3];
    int tot = c0 + c1 + c2 + c3;
    int incl = tot;
    #pragma unroll
    for (int off = 1; off < 32; off <<= 1) {
        int nv = __shfl_up_sync(0xffffffffu, incl, off, 32);
        if (lane >= off) incl += nv;
    }
    if (lane == 31) wsum[wid] = incl;
    __syncthreads();
    if (tid == 0) {
        int r = 0;
        #pragma unroll
        for (int w = 0; w < 8; ++w) { int v = wsum[w]; wsum[w] = r; r += v; }
    }
    __syncthreads();
    int ex = incl - tot + wsum[wid];
    bstart[tid * 4]     = ex;
    bstart[tid * 4 + 1] = ex + c0;
    bstart[tid * 4 + 2] = ex + c0 + c1;
    bstart[tid * 4 + 3] = ex + c0 + c1 + c2;
    if (tid == 0) bstart[KR] = TOK;
    __syncthreads();
    cnt[tid * 4]     = ex;
    cnt[tid * 4 + 1] = ex + c0;
    cnt[tid * 4 + 2] = ex + c0 + c1;
    cnt[tid * 4 + 3] = ex + c0 + c1 + c2;
    __syncthreads();

    for (int t = tid; t < TOK; t += 256) {
        int k = g_kid[base + t];
        int p = atomicAdd(&cnt[k], 1);
        kpos[p] = t;
    }
    __syncthreads();

    for (int b = tid; b < KR; b += 256) {
        int lo = bstart[b], hi = bstart[b + 1];
        for (int i = lo + 1; i < hi; ++i) {
            int v = kpos[i], j = i - 1;
            while (j >= lo && kpos[j] > v) { kpos[j + 1] = kpos[j]; --j; }
            kpos[j + 1] = v;
        }
    }
    __syncthreads();

    for (int t = tid; t < TOK; t += 256) {
        int q = g_qid[base + t];
        int lo = bstart[q], hi = bstart[q + 1];
        int best = -1;
        for (int i = hi - 1; i >= lo; --i) {
            if (kpos[i] < t) { best = kpos[i]; break; }
        }
        g_row[base + t] = (best >= 0) ? (g_vid[base + best] + 1) : 0;
    }
}

// ---------------------------------------------------------------------------
// Embedding gather. grid = (TOK/128, NHEAD), block = 256.
// ---------------------------------------------------------------------------
__global__ __launch_bounds__(256) void gather_kernel(
    const float* __restrict__ emb, float* __restrict__ out)
{
    const int m = blockIdx.y, t0 = blockIdx.x * 128;
    const float* E = emb + (size_t)m * (KR + 1) * DDIM;
    for (int j = threadIdx.x; j < 128 * 16; j += 256) {
        int t = j >> 4, dg = j & 15;
        int row = g_row[m * TOK + t0 + t];
        float4 v;
        if (row) {
            v = *reinterpret_cast<const float4*>(E + (size_t)row * DDIM + dg * 4);
        } else {
            v = make_float4(0.f, 0.f, 0.f, 0.f);   // padding row is zero
        }
        *reinterpret_cast<float4*>(out + (size_t)(t0 + t) * CDIM + m * DDIM + dg * 4) = v;
    }
}

// ---------------------------------------------------------------------------
extern "C" void kernel_launch(void* const* d_in, const int* in_sizes, int n_in,
                              void* d_out, int out_size)
{
    (void)in_sizes; (void)n_in; (void)out_size;
    const float* x   = (const float*)d_in[0];
    const float* wq  = (const float*)d_in[1];
    const float* wk  = (const float*)d_in[2];
    const float* wv  = (const float*)d_in[3];
    const float* emb = (const float*)d_in[4];
    float* out = (float*)d_out;

    cudaFuncSetAttribute(tc_route_kernel,
                         cudaFuncAttributeMaxDynamicSharedMemorySize, SM_TOTAL);

    split_w_kernel<<<(3 * NHEAD * NTPM * 4 * 32) / 256, 256>>>(wq, wk, wv);
    dim3 g1(TOK / CTOK, NHEAD);
    tc_route_kernel<<<g1, 256, SM_TOTAL>>>(x);
    match_kernel<<<NHEAD, 256>>>();
    dim3 g3(TOK / 128, NHEAD);
    gather_kernel<<<g3, 256>>>(emb, out);
}

// round 10
// speedup vs baseline: 8.6102x; 1.1320x over previous
#include <cuda_runtime.h>
#include <cuda_fp16.h>
#include <cstdint>

#define TOK   2048
#define CDIM  2048
#define NHEAD 32
#define DDIM  64
#define KR    1024

#define CTOK  256            // tokens per x tile
#define NTPM  128            // 8-col n-tiles per matrix
#define GSZ   8              // n-tiles per pipeline group
#define CHNT  48             // n-tiles per work unit (6 groups)
#define NUNIT 2048           // 8 tiles x 32 heads x 8 chunks
#define NCTA  296            // exactly 2 CTAs per SM on 148 SMs
#define NT_B  2048           // bytes per n-tile (hi/lo interleaved 16B)
#define GRP_B (GSZ * NT_B)   // 16 KB

#define SM_XPIT 68
#define SM_B    (CTOK * SM_XPIT * 4)          // 69632
#define SM_TOTAL (SM_B + 2 * GRP_B)           // 102400 -> 2 CTAs/SM

__device__ int g_row[NHEAD * TOK];
__device__ unsigned long long g_best[(size_t)3 * NHEAD * TOK];
// W fp16 hi/lo interleaved, fragment-major: [mat][head][ntl][ks][lane]{h0,h1,l0,l1}
__device__ __align__(16) uint8_t g_whf[(size_t)3 * NHEAD * NTPM * NT_B];   // 24 MB

// ---------------- helpers ----------------
static __device__ __forceinline__ uint32_t s2u(const void* p) {
    uint32_t a;
    asm("{ .reg .u64 t; cvta.to.shared.u64 t, %1; cvt.u32.u64 %0, t; }"
        : "=r"(a) : "l"(p));
    return a;
}
static __device__ __forceinline__ uint32_t h2u(__half2 h) {
    uint32_t u; asm("mov.b32 %0, %1;" : "=r"(u) : "r"(*(uint32_t*)&h)); return u;
}
static __device__ __forceinline__ void mma_f16(float* d, const uint32_t* a,
                                               uint32_t b0, uint32_t b1) {
    asm volatile("mma.sync.aligned.m16n8k16.row.col.f32.f16.f16.f32 "
                 "{%0,%1,%2,%3}, {%4,%5,%6,%7}, {%8,%9}, {%0,%1,%2,%3};"
                 : "+f"(d[0]), "+f"(d[1]), "+f"(d[2]), "+f"(d[3])
                 : "r"(a[0]), "r"(a[1]), "r"(a[2]), "r"(a[3]),
                   "r"(b0), "r"(b1));
}
static __device__ __forceinline__ void cp16(uint32_t d, const void* s) {
    asm volatile("cp.async.cg.shared.global [%0], [%1], 16;"
                 :: "r"(d), "l"(s) : "memory");
}
#define CP_COMMIT() asm volatile("cp.async.commit_group;" ::: "memory")
#define CP_WAIT1()  asm volatile("cp.async.wait_group 1;" ::: "memory")
#define CP_WAIT0()  asm volatile("cp.async.wait_group 0;" ::: "memory")

// split one float pair into packed fp16 hi / lo
static __device__ __forceinline__ void split2(float2 v, uint32_t& h, uint32_t& l) {
    __half2 hh = __float22half2_rn(v);
    float2 hf = __half22float2(hh);
    __half2 ll = __float22half2_rn(make_float2(v.x - hf.x, v.y - hf.y));
    h = h2u(hh); l = h2u(ll);
}
// orderable packing: larger logit wins; tie -> smaller col wins; 0 < any real
static __device__ __forceinline__ unsigned long long packcmp(float v, int col) {
    uint32_t b = __float_as_uint(v);
    uint32_t u = (b & 0x80000000u) ? ~b : (b | 0x80000000u);
    return ((unsigned long long)u << 32)
         | (unsigned long long)(0xFFFFFFFFu - (uint32_t)col);
}
static __device__ __forceinline__ int unpack_col(unsigned long long p) {
    return (int)(0xFFFFFFFFu - (uint32_t)(p & 0xFFFFFFFFull));
}

// ---------------------------------------------------------------------------
__global__ __launch_bounds__(256) void zero_best_kernel()
{
    g_best[blockIdx.x * 256u + threadIdx.x] = 0ull;
}

// ---------------------------------------------------------------------------
// Prepass: split W into fp16 hi/lo, fragment-major, hi/lo interleaved 16B.
// id bits: lane[0:5) ks[5:7) ntl[7:14) head[14:19) mat[19:21)
// ---------------------------------------------------------------------------
__global__ __launch_bounds__(256) void split_w_kernel(
    const float* __restrict__ wq, const float* __restrict__ wk,
    const float* __restrict__ wv)
{
    uint32_t id = blockIdx.x * 256u + threadIdx.x;
    uint32_t lane = id & 31u;
    uint32_t ks   = (id >> 5) & 3u;
    uint32_t ntl  = (id >> 7) & 127u;
    uint32_t head = (id >> 14) & 31u;
    uint32_t mat  = id >> 19;
    const float* W = (mat == 0) ? wq : (mat == 1) ? wk : wv;
    int col = (int)(ntl * 8 + (lane >> 2));
    int k0  = (int)(ks * 16 + 2 * (lane & 3));
    size_t off = ((size_t)head * KR + col) * DDIM + k0;
    float2 v0 = *reinterpret_cast<const float2*>(W + off);
    float2 v1 = *reinterpret_cast<const float2*>(W + off + 8);
    uint32_t h0, l0, h1, l1;
    split2(v0, h0, l0);
    split2(v1, h1, l1);
    uint4 o; o.x = h0; o.y = h1; o.z = l0; o.w = l1;
    *reinterpret_cast<uint4*>(g_whf + (size_t)id * 16) = o;
}

// ---------------------------------------------------------------------------
// Route kernel: 2-split fp16 mma argmax-GEMM, occupancy-exact partition.
// grid = 296 (2 CTAs/SM), block = 256. CTA i owns units [i*2048/296,(i+1)*2048/296).
// unit u: t8 = u>>8, head = (u>>3)&31, chunk = u&7 (48 n-tiles).
// Partial argmax merged via atomicMax on packed u64.
// ---------------------------------------------------------------------------
__global__ __launch_bounds__(256, 2) void tc_route_kernel(const float* __restrict__ x)
{
    extern __shared__ uint8_t smem[];
    float* xs = reinterpret_cast<float*>(smem);
    const uint32_t sbB = s2u(smem) + SM_B;

    const int tid = threadIdx.x, lane = tid & 31, wid = tid >> 5;
    const int u0 = (int)(((long long)blockIdx.x * NUNIT) / NCTA);
    const int u1 = (int)(((long long)(blockIdx.x + 1) * NUNIT) / NCTA);

    uint32_t ah[2][4][4], al[2][4][4];
    int cur_th = -1;
    int head = 0, t0 = 0;

    float bmax[4]; int bidx[4];
    #pragma unroll
    for (int sl = 0; sl < 4; ++sl) { bmax[sl] = -3.402823466e38f; bidx[sl] = 0; }

    for (int u = u0; u < u1; ++u) {
        const int th = u >> 3;
        const int chunk = u & 7;
        if (th != cur_th) {
            cur_th = th;
            head = th & 31;
            t0 = (th >> 5) * CTOK;
            __syncthreads();   // all warps done with previous compute / xs reads
            for (int i = tid; i < CTOK * 16; i += 256) {
                int t = i >> 4, c = i & 15;
                float4 v = *reinterpret_cast<const float4*>(
                    x + (size_t)(t0 + t) * CDIM + head * DDIM + c * 4);
                *reinterpret_cast<float4*>(&xs[t * SM_XPIT + c * 4]) = v;
            }
            __syncthreads();
            const int r0 = wid * 32 + (lane >> 2);
            #pragma unroll
            for (int mt = 0; mt < 2; ++mt)
                #pragma unroll
                for (int ks = 0; ks < 4; ++ks)
                    #pragma unroll
                    for (int e = 0; e < 4; ++e) {
                        int row = r0 + mt * 16 + (e & 1) * 8;
                        int kc  = ks * 16 + 2 * (lane & 3) + (e >> 1) * 8;
                        float2 v = *reinterpret_cast<const float2*>(
                            &xs[row * SM_XPIT + kc]);
                        split2(v, ah[mt][ks][e], al[mt][ks][e]);
                    }
        }

        const int F0u = chunk * CHNT;
        auto stage = [&](int gi) {
            int F0 = F0u + gi * GSZ;
            int mat = F0 >> 7, ntl0 = F0 & (NTPM - 1);
            const uint8_t* src = g_whf
                + (((size_t)mat * NHEAD + head) * NTPM + ntl0) * NT_B + tid * 16;
            uint32_t dst = sbB + (uint32_t)(gi & 1) * GRP_B + tid * 16;
            #pragma unroll
            for (int j = 0; j < 4; ++j)
                cp16(dst + j * 4096u, src + (size_t)j * 4096);
        };

        stage(0); CP_COMMIT();

        #pragma unroll 1
        for (int gi = 0; gi < CHNT / GSZ; ++gi) {
            if (gi + 1 < CHNT / GSZ) { stage(gi + 1); CP_COMMIT(); CP_WAIT1(); }
            else                     { CP_WAIT0(); }
            __syncthreads();

            const uint32_t bb = sbB + (uint32_t)(gi & 1) * GRP_B
                              + (uint32_t)lane * 16u;
            #pragma unroll 2
            for (int ntg = 0; ntg < GSZ; ++ntg) {
                const int F = F0u + gi * GSZ + ntg;
                float d0[4] = {0.f, 0.f, 0.f, 0.f};
                float d1[4] = {0.f, 0.f, 0.f, 0.f};
                const uint32_t tb = bb + (uint32_t)ntg * NT_B;
                #pragma unroll
                for (int ks = 0; ks < 4; ++ks) {
                    uint32_t bh0, bh1, bl0, bl1;
                    asm volatile("ld.shared.v4.b32 {%0,%1,%2,%3}, [%4];"
                                 : "=r"(bh0), "=r"(bh1), "=r"(bl0), "=r"(bl1)
                                 : "r"(tb + ks * 512u));
                    mma_f16(d0, ah[0][ks], bh0, bh1);   // hh
                    mma_f16(d0, al[0][ks], bh0, bh1);   // lh
                    mma_f16(d0, ah[0][ks], bl0, bl1);   // hl
                    mma_f16(d1, ah[1][ks], bh0, bh1);
                    mma_f16(d1, al[1][ks], bh0, bh1);
                    mma_f16(d1, ah[1][ks], bl0, bl1);
                }
                const int cb = (F & (NTPM - 1)) * 8 + 2 * (lane & 3);
                if (d0[0] > bmax[0]) { bmax[0] = d0[0]; bidx[0] = cb; }
                if (d0[1] > bmax[0]) { bmax[0] = d0[1]; bidx[0] = cb + 1; }
                if (d0[2] > bmax[1]) { bmax[1] = d0[2]; bidx[1] = cb; }
                if (d0[3] > bmax[1]) { bmax[1] = d0[3]; bidx[1] = cb + 1; }
                if (d1[0] > bmax[2]) { bmax[2] = d1[0]; bidx[2] = cb; }
                if (d1[1] > bmax[2]) { bmax[2] = d1[1]; bidx[2] = cb + 1; }
                if (d1[2] > bmax[3]) { bmax[3] = d1[2]; bidx[3] = cb; }
                if (d1[3] > bmax[3]) { bmax[3] = d1[3]; bidx[3] = cb + 1; }

                // flush at matrix boundary or unit end
                if ((F & (NTPM - 1)) == NTPM - 1 || F == F0u + CHNT - 1) {
                    const int mat = F >> 7;
                    unsigned long long* B =
                        g_best + ((size_t)mat * NHEAD + head) * TOK + t0;
                    #pragma unroll
                    for (int sl = 0; sl < 4; ++sl) {
                        float bv = bmax[sl]; int bi = bidx[sl];
                        #pragma unroll
                        for (int off = 1; off < 4; off <<= 1) {
                            float om = __shfl_xor_sync(0xffffffffu, bv, off, 32);
                            int   oi = __shfl_xor_sync(0xffffffffu, bi, off, 32);
                            if (om > bv || (om == bv && oi < bi)) {
                                bv = om; bi = oi;
                            }
                        }
                        if ((lane & 3) == 0) {
                            int row = wid * 32 + (lane >> 2)
                                    + (sl >> 1) * 16 + (sl & 1) * 8;
                            atomicMax(&B[row], packcmp(bv, bi));
                        }
                        bmax[sl] = -3.402823466e38f; bidx[sl] = 0;
                    }
                }
            }
            __syncthreads();
        }
    }
}

// ---------------------------------------------------------------------------
// tau matching via bucketed counting sort; ids decoded from g_best.
// grid = NHEAD, block = 256.
// ---------------------------------------------------------------------------
__global__ __launch_bounds__(256) void match_kernel()
{
    __shared__ int cnt[KR];
    __shared__ int bstart[KR + 1];
    __shared__ int kpos[TOK];
    __shared__ int wsum[8];

    const int m = blockIdx.x, tid = threadIdx.x;
    const int lane = tid & 31, wid = tid >> 5;
    const unsigned long long* bq = g_best + (size_t)(0 * NHEAD + m) * TOK;
    const unsigned long long* bk = g_best + (size_t)(1 * NHEAD + m) * TOK;
    const unsigned long long* bv = g_best + (size_t)(2 * NHEAD + m) * TOK;

    for (int i = tid; i < KR; i += 256) cnt[i] = 0;
    __syncthreads();
    for (int t = tid; t < TOK; t += 256) atomicAdd(&cnt[unpack_col(bk[t])], 1);
    __syncthreads();

    int c0 = cnt[tid * 4], c1 = cnt[tid * 4 + 1],
        c2 = cnt[tid * 4 + 2], c3 = cnt[tid * 4 + 3];
    int tot = c0 + c1 + c2 + c3;
    int incl = tot;
    #pragma unroll
    for (int off = 1; off < 32; off <<= 1) {
        int nv = __shfl_up_sync(0xffffffffu, incl, off, 32);
        if (lane >= off) incl += nv;
    }
    if (lane == 31) wsum[wid] = incl;
    __syncthreads();
    if (tid == 0) {
        int r = 0;
        #pragma unroll
        for (int w = 0; w < 8; ++w) { int v = wsum[w]; wsum[w] = r; r += v; }
    }
    __syncthreads();
    int ex = incl - tot + wsum[wid];
    bstart[tid * 4]     = ex;
    bstart[tid * 4 + 1] = ex + c0;
    bstart[tid * 4 + 2] = ex + c0 + c1;
    bstart[tid * 4 + 3] = ex + c0 + c1 + c2;
    if (tid == 0) bstart[KR] = TOK;
    __syncthreads();
    cnt[tid * 4]     = ex;
    cnt[tid * 4 + 1] = ex + c0;
    cnt[tid * 4 + 2] = ex + c0 + c1;
    cnt[tid * 4 + 3] = ex + c0 + c1 + c2;
    __syncthreads();

    for (int t = tid; t < TOK; t += 256) {
        int k = unpack_col(bk[t]);
        int p = atomicAdd(&cnt[k], 1);
        kpos[p] = t;
    }
    __syncthreads();

    for (int b = tid; b < KR; b += 256) {
        int lo = bstart[b], hi = bstart[b + 1];
        for (int i = lo + 1; i < hi; ++i) {
            int v = kpos[i], j = i - 1;
            while (j >= lo && kpos[j] > v) { kpos[j + 1] = kpos[j]; --j; }
            kpos[j + 1] = v;
        }
    }
    __syncthreads();

    for (int t = tid; t < TOK; t += 256) {
        int q = unpack_col(bq[t]);
        int lo = bstart[q], hi = bstart[q + 1];
        int best = -1;
        for (int i = hi - 1; i >= lo; --i) {
            if (kpos[i] < t) { best = kpos[i]; break; }
        }
        g_row[m * TOK + t] = (best >= 0) ? (unpack_col(bv[best]) + 1) : 0;
    }
}

// ---------------------------------------------------------------------------
// Embedding gather. grid = (TOK/128, NHEAD), block = 256.
// ---------------------------------------------------------------------------
__global__ __launch_bounds__(256) void gather_kernel(
    const float* __restrict__ emb, float* __restrict__ out)
{
    const int m = blockIdx.y, t0 = blockIdx.x * 128;
    const float* E = emb + (size_t)m * (KR + 1) * DDIM;
    for (int j = threadIdx.x; j < 128 * 16; j += 256) {
        int t = j >> 4, dg = j & 15;
        int row = g_row[m * TOK + t0 + t];
        float4 v;
        if (row) {
            v = *reinterpret_cast<const float4*>(E + (size_t)row * DDIM + dg * 4);
        } else {
            v = make_float4(0.f, 0.f, 0.f, 0.f);   // padding row is zero
        }
        *reinterpret_cast<float4*>(out + (size_t)(t0 + t) * CDIM + m * DDIM + dg * 4) = v;
    }
}

// ---------------------------------------------------------------------------
extern "C" void kernel_launch(void* const* d_in, const int* in_sizes, int n_in,
                              void* d_out, int out_size)
{
    (void)in_sizes; (void)n_in; (void)out_size;
    const float* x   = (const float*)d_in[0];
    const float* wq  = (const float*)d_in[1];
    const float* wk  = (const float*)d_in[2];
    const float* wv  = (const float*)d_in[3];
    const float* emb = (const float*)d_in[4];
    float* out = (float*)d_out;

    cudaFuncSetAttribute(tc_route_kernel,
                         cudaFuncAttributeMaxDynamicSharedMemorySize, SM_TOTAL);

    zero_best_kernel<<<(3 * NHEAD * TOK) / 256, 256>>>();
    split_w_kernel<<<(3 * NHEAD * NTPM * 4 * 32) / 256, 256>>>(wq, wk, wv);
    tc_route_kernel<<<NCTA, 256, SM_TOTAL>>>(x);
    match_kernel<<<NHEAD, 256>>>();
    dim3 g3(TOK / 128, NHEAD);
    gather_kernel<<<g3, 256>>>(emb, out);
}

// round 11
// speedup vs baseline: 8.9365x; 1.0379x over previous
#include <cuda_runtime.h>
#include <cuda_fp16.h>
#include <cstdint>

#define TOK   2048
#define CDIM  2048
#define NHEAD 32
#define DDIM  64
#define KR    1024

#define CTOK  256            // tokens per x tile
#define NTPM  128            // 8-col n-tiles per matrix
#define GSZ   8              // n-tiles per pipeline group
#define CHNT  48             // n-tiles per work unit (6 groups)
#define NUNIT 2048           // 8 tiles x 32 heads x 8 chunks
#define NCTA  296            // exactly 2 CTAs per SM on 148 SMs
#define NT_B  2048           // bytes per n-tile (hi/lo interleaved 16B)
#define GRP_B (GSZ * NT_B)   // 16 KB

#define SM_XPIT 68
#define SM_B    (CTOK * SM_XPIT * 4)          // 69632
#define SM_TOTAL (SM_B + 2 * GRP_B)           // 102400 -> 2 CTAs/SM

__device__ int g_row[NHEAD * TOK];
__device__ unsigned long long g_best[(size_t)3 * NHEAD * TOK];
// W fp16 hi/lo interleaved, fragment-major: [mat][head][ntl][ks][lane]{h0,h1,l0,l1}
__device__ __align__(16) uint8_t g_whf[(size_t)3 * NHEAD * NTPM * NT_B];   // 24 MB

// ---------------- helpers ----------------
static __device__ __forceinline__ uint32_t s2u(const void* p) {
    uint32_t a;
    asm("{ .reg .u64 t; cvta.to.shared.u64 t, %1; cvt.u32.u64 %0, t; }"
        : "=r"(a) : "l"(p));
    return a;
}
static __device__ __forceinline__ uint32_t h2u(__half2 h) {
    uint32_t u; asm("mov.b32 %0, %1;" : "=r"(u) : "r"(*(uint32_t*)&h)); return u;
}
static __device__ __forceinline__ void mma_f16(float* d, const uint32_t* a,
                                               uint32_t b0, uint32_t b1) {
    asm volatile("mma.sync.aligned.m16n8k16.row.col.f32.f16.f16.f32 "
                 "{%0,%1,%2,%3}, {%4,%5,%6,%7}, {%8,%9}, {%0,%1,%2,%3};"
                 : "+f"(d[0]), "+f"(d[1]), "+f"(d[2]), "+f"(d[3])
                 : "r"(a[0]), "r"(a[1]), "r"(a[2]), "r"(a[3]),
                   "r"(b0), "r"(b1));
}
static __device__ __forceinline__ void cp16(uint32_t d, const void* s) {
    asm volatile("cp.async.cg.shared.global [%0], [%1], 16;"
                 :: "r"(d), "l"(s) : "memory");
}
#define CP_COMMIT() asm volatile("cp.async.commit_group;" ::: "memory")
#define CP_WAIT1()  asm volatile("cp.async.wait_group 1;" ::: "memory")
#define CP_WAIT0()  asm volatile("cp.async.wait_group 0;" ::: "memory")

// split one float pair into packed fp16 hi / lo
static __device__ __forceinline__ void split2(float2 v, uint32_t& h, uint32_t& l) {
    __half2 hh = __float22half2_rn(v);
    float2 hf = __half22float2(hh);
    __half2 ll = __float22half2_rn(make_float2(v.x - hf.x, v.y - hf.y));
    h = h2u(hh); l = h2u(ll);
}
// orderable packing: larger logit wins; tie -> smaller col wins; 0 < any real
static __device__ __forceinline__ unsigned long long packcmp(float v, int col) {
    uint32_t b = __float_as_uint(v);
    uint32_t u = (b & 0x80000000u) ? ~b : (b | 0x80000000u);
    return ((unsigned long long)u << 32)
         | (unsigned long long)(0xFFFFFFFFu - (uint32_t)col);
}
static __device__ __forceinline__ int unpack_col(unsigned long long p) {
    return (int)(0xFFFFFFFFu - (uint32_t)(p & 0xFFFFFFFFull));
}

// ---------------------------------------------------------------------------
// Prepass: split W into fp16 hi/lo, fragment-major, hi/lo interleaved 16B.
// id bits: lane[0:5) ks[5:7) ntl[7:14) head[14:19) mat[19:21)
// Also zeroes g_best (first 196608 threads).
// ---------------------------------------------------------------------------
__global__ __launch_bounds__(256) void split_w_kernel(
    const float* __restrict__ wq, const float* __restrict__ wk,
    const float* __restrict__ wv)
{
    uint32_t id = blockIdx.x * 256u + threadIdx.x;
    if (id < 3u * NHEAD * TOK) g_best[id] = 0ull;
    uint32_t lane = id & 31u;
    uint32_t ks   = (id >> 5) & 3u;
    uint32_t ntl  = (id >> 7) & 127u;
    uint32_t head = (id >> 14) & 31u;
    uint32_t mat  = id >> 19;
    const float* W = (mat == 0) ? wq : (mat == 1) ? wk : wv;
    int col = (int)(ntl * 8 + (lane >> 2));
    int k0  = (int)(ks * 16 + 2 * (lane & 3));
    size_t off = ((size_t)head * KR + col) * DDIM + k0;
    float2 v0 = *reinterpret_cast<const float2*>(W + off);
    float2 v1 = *reinterpret_cast<const float2*>(W + off + 8);
    uint32_t h0, l0, h1, l1;
    split2(v0, h0, l0);
    split2(v1, h1, l1);
    uint4 o; o.x = h0; o.y = h1; o.z = l0; o.w = l1;
    *reinterpret_cast<uint4*>(g_whf + (size_t)id * 16) = o;
}

// ---------------------------------------------------------------------------
// Route kernel: 2-split fp16 mma argmax-GEMM, occupancy-exact partition.
// grid = 296 (2 CTAs/SM), block = 256. CTA i owns units [i*2048/296,(i+1)*2048/296).
// unit u: t8 = u>>8, head = (u>>3)&31, chunk = u&7 (48 n-tiles).
// Partial argmax merged via atomicMax on packed u64.
// ---------------------------------------------------------------------------
__global__ __launch_bounds__(256, 2) void tc_route_kernel(const float* __restrict__ x)
{
    extern __shared__ uint8_t smem[];
    float* xs = reinterpret_cast<float*>(smem);
    const uint32_t sbB = s2u(smem) + SM_B;

    const int tid = threadIdx.x, lane = tid & 31, wid = tid >> 5;
    const int u0 = (int)(((long long)blockIdx.x * NUNIT) / NCTA);
    const int u1 = (int)(((long long)(blockIdx.x + 1) * NUNIT) / NCTA);

    uint32_t ah[2][4][4], al[2][4][4];
    int cur_th = -1;
    int head = 0, t0 = 0;

    float bmax[4]; int bidx[4];
    #pragma unroll
    for (int sl = 0; sl < 4; ++sl) { bmax[sl] = -3.402823466e38f; bidx[sl] = 0; }

    for (int u = u0; u < u1; ++u) {
        const int th = u >> 3;
        const int chunk = u & 7;
        if (th != cur_th) {
            cur_th = th;
            head = th & 31;
            t0 = (th >> 5) * CTOK;
            __syncthreads();   // all warps done with previous compute / xs reads
            for (int i = tid; i < CTOK * 16; i += 256) {
                int t = i >> 4, c = i & 15;
                float4 v = *reinterpret_cast<const float4*>(
                    x + (size_t)(t0 + t) * CDIM + head * DDIM + c * 4);
                *reinterpret_cast<float4*>(&xs[t * SM_XPIT + c * 4]) = v;
            }
            __syncthreads();
            const int r0 = wid * 32 + (lane >> 2);
            #pragma unroll
            for (int mt = 0; mt < 2; ++mt)
                #pragma unroll
                for (int ks = 0; ks < 4; ++ks)
                    #pragma unroll
                    for (int e = 0; e < 4; ++e) {
                        int row = r0 + mt * 16 + (e & 1) * 8;
                        int kc  = ks * 16 + 2 * (lane & 3) + (e >> 1) * 8;
                        float2 v = *reinterpret_cast<const float2*>(
                            &xs[row * SM_XPIT + kc]);
                        split2(v, ah[mt][ks][e], al[mt][ks][e]);
                    }
        }

        const int F0u = chunk * CHNT;
        auto stage = [&](int gi) {
            int F0 = F0u + gi * GSZ;
            int mat = F0 >> 7, ntl0 = F0 & (NTPM - 1);
            const uint8_t* src = g_whf
                + (((size_t)mat * NHEAD + head) * NTPM + ntl0) * NT_B + tid * 16;
            uint32_t dst = sbB + (uint32_t)(gi & 1) * GRP_B + tid * 16;
            #pragma unroll
            for (int j = 0; j < 4; ++j)
                cp16(dst + j * 4096u, src + (size_t)j * 4096);
        };

        stage(0); CP_COMMIT();

        #pragma unroll 1
        for (int gi = 0; gi < CHNT / GSZ; ++gi) {
            if (gi + 1 < CHNT / GSZ) { stage(gi + 1); CP_COMMIT(); CP_WAIT1(); }
            else                     { CP_WAIT0(); }
            __syncthreads();

            const uint32_t bb = sbB + (uint32_t)(gi & 1) * GRP_B
                              + (uint32_t)lane * 16u;
            #pragma unroll 2
            for (int ntg = 0; ntg < GSZ; ++ntg) {
                const int F = F0u + gi * GSZ + ntg;
                float d0[4] = {0.f, 0.f, 0.f, 0.f};
                float d1[4] = {0.f, 0.f, 0.f, 0.f};
                const uint32_t tb = bb + (uint32_t)ntg * NT_B;
                #pragma unroll
                for (int ks = 0; ks < 4; ++ks) {
                    uint32_t bh0, bh1, bl0, bl1;
                    asm volatile("ld.shared.v4.b32 {%0,%1,%2,%3}, [%4];"
                                 : "=r"(bh0), "=r"(bh1), "=r"(bl0), "=r"(bl1)
                                 : "r"(tb + ks * 512u));
                    mma_f16(d0, ah[0][ks], bh0, bh1);   // hh
                    mma_f16(d0, al[0][ks], bh0, bh1);   // lh
                    mma_f16(d0, ah[0][ks], bl0, bl1);   // hl
                    mma_f16(d1, ah[1][ks], bh0, bh1);
                    mma_f16(d1, al[1][ks], bh0, bh1);
                    mma_f16(d1, ah[1][ks], bl0, bl1);
                }
                const int cb = (F & (NTPM - 1)) * 8 + 2 * (lane & 3);
                if (d0[0] > bmax[0]) { bmax[0] = d0[0]; bidx[0] = cb; }
                if (d0[1] > bmax[0]) { bmax[0] = d0[1]; bidx[0] = cb + 1; }
                if (d0[2] > bmax[1]) { bmax[1] = d0[2]; bidx[1] = cb; }
                if (d0[3] > bmax[1]) { bmax[1] = d0[3]; bidx[1] = cb + 1; }
                if (d1[0] > bmax[2]) { bmax[2] = d1[0]; bidx[2] = cb; }
                if (d1[1] > bmax[2]) { bmax[2] = d1[1]; bidx[2] = cb + 1; }
                if (d1[2] > bmax[3]) { bmax[3] = d1[2]; bidx[3] = cb; }
                if (d1[3] > bmax[3]) { bmax[3] = d1[3]; bidx[3] = cb + 1; }

                // flush at matrix boundary or unit end
                if ((F & (NTPM - 1)) == NTPM - 1 || F == F0u + CHNT - 1) {
                    const int mat = F >> 7;
                    unsigned long long* B =
                        g_best + ((size_t)mat * NHEAD + head) * TOK + t0;
                    #pragma unroll
                    for (int sl = 0; sl < 4; ++sl) {
                        float bv = bmax[sl]; int bi = bidx[sl];
                        #pragma unroll
                        for (int off = 1; off < 4; off <<= 1) {
                            float om = __shfl_xor_sync(0xffffffffu, bv, off, 32);
                            int   oi = __shfl_xor_sync(0xffffffffu, bi, off, 32);
                            if (om > bv || (om == bv && oi < bi)) {
                                bv = om; bi = oi;
                            }
                        }
                        if ((lane & 3) == 0) {
                            int row = wid * 32 + (lane >> 2)
                                    + (sl >> 1) * 16 + (sl & 1) * 8;
                            atomicMax(&B[row], packcmp(bv, bi));
                        }
                        bmax[sl] = -3.402823466e38f; bidx[sl] = 0;
                    }
                }
            }
            __syncthreads();
        }
    }
}

// ---------------------------------------------------------------------------
// tau matching via bucketed counting sort; ids decoded from g_best.
// grid = NHEAD, block = 1024 (short serial chains per phase).
// ---------------------------------------------------------------------------
__global__ __launch_bounds__(1024) void match_kernel()
{
    __shared__ int cnt[KR];
    __shared__ int bstart[KR + 1];
    __shared__ int kpos[TOK];
    __shared__ int wsum[32];
    __shared__ int kid_s[TOK];

    const int m = blockIdx.x, tid = threadIdx.x;
    const int lane = tid & 31, wid = tid >> 5;
    const unsigned long long* bq = g_best + (size_t)(0 * NHEAD + m) * TOK;
    const unsigned long long* bk = g_best + (size_t)(1 * NHEAD + m) * TOK;
    const unsigned long long* bv = g_best + (size_t)(2 * NHEAD + m) * TOK;

    cnt[tid] = 0;
    int k0 = unpack_col(bk[tid]);
    int k1 = unpack_col(bk[tid + 1024]);
    kid_s[tid] = k0;
    kid_s[tid + 1024] = k1;
    __syncthreads();
    atomicAdd(&cnt[k0], 1);
    atomicAdd(&cnt[k1], 1);
    __syncthreads();

    // exclusive prefix over 1024 counters, 1 per thread
    int c = cnt[tid];
    int incl = c;
    #pragma unroll
    for (int off = 1; off < 32; off <<= 1) {
        int nv = __shfl_up_sync(0xffffffffu, incl, off, 32);
        if (lane >= off) incl += nv;
    }
    if (lane == 31) wsum[wid] = incl;
    __syncthreads();
    if (wid == 0) {
        int v = wsum[lane];
        int wincl = v;
        #pragma unroll
        for (int off = 1; off < 32; off <<= 1) {
            int nv = __shfl_up_sync(0xffffffffu, wincl, off, 32);
            if (lane >= off) wincl += nv;
        }
        wsum[lane] = wincl - v;   // exclusive
    }
    __syncthreads();
    int ex = incl - c + wsum[wid];
    bstart[tid] = ex;
    if (tid == 0) bstart[KR] = TOK;
    __syncthreads();
    cnt[tid] = ex;   // scatter cursor
    __syncthreads();

    {
        int p = atomicAdd(&cnt[k0], 1);
        kpos[p] = tid;
        int p1 = atomicAdd(&cnt[k1], 1);
        kpos[p1] = tid + 1024;
    }
    __syncthreads();

    // sort each bucket ascending (1 bucket per thread, avg size 2)
    {
        int lo = bstart[tid], hi = bstart[tid + 1];
        for (int i = lo + 1; i < hi; ++i) {
            int v = kpos[i], j = i - 1;
            while (j >= lo && kpos[j] > v) { kpos[j + 1] = kpos[j]; --j; }
            kpos[j + 1] = v;
        }
    }
    __syncthreads();

    #pragma unroll
    for (int h = 0; h < 2; ++h) {
        int t = tid + h * 1024;
        int q = unpack_col(bq[t]);
        int lo = bstart[q], hi = bstart[q + 1];
        int best = -1;
        for (int i = hi - 1; i >= lo; --i) {
            if (kpos[i] < t) { best = kpos[i]; break; }
        }
        g_row[m * TOK + t] = (best >= 0) ? (unpack_col(bv[best]) + 1) : 0;
    }
}

// ---------------------------------------------------------------------------
// Embedding gather. grid = (TOK/128, NHEAD), block = 256.
// ---------------------------------------------------------------------------
__global__ __launch_bounds__(256) void gather_kernel(
    const float* __restrict__ emb, float* __restrict__ out)
{
    const int m = blockIdx.y, t0 = blockIdx.x * 128;
    const float* E = emb + (size_t)m * (KR + 1) * DDIM;
    for (int j = threadIdx.x; j < 128 * 16; j += 256) {
        int t = j >> 4, dg = j & 15;
        int row = g_row[m * TOK + t0 + t];
        float4 v;
        if (row) {
            v = *reinterpret_cast<const float4*>(E + (size_t)row * DDIM + dg * 4);
        } else {
            v = make_float4(0.f, 0.f, 0.f, 0.f);   // padding row is zero
        }
        *reinterpret_cast<float4*>(out + (size_t)(t0 + t) * CDIM + m * DDIM + dg * 4) = v;
    }
}

// ---------------------------------------------------------------------------
extern "C" void kernel_launch(void* const* d_in, const int* in_sizes, int n_in,
                              void* d_out, int out_size)
{
    (void)in_sizes; (void)n_in; (void)out_size;
    const float* x   = (const float*)d_in[0];
    const float* wq  = (const float*)d_in[1];
    const float* wk  = (const float*)d_in[2];
    const float* wv  = (const float*)d_in[3];
    const float* emb = (const float*)d_in[4];
    float* out = (float*)d_out;

    cudaFuncSetAttribute(tc_route_kernel,
                         cudaFuncAttributeMaxDynamicSharedMemorySize, SM_TOTAL);

    split_w_kernel<<<(3 * NHEAD * NTPM * 4 * 32) / 256, 256>>>(wq, wk, wv);
    tc_route_kernel<<<NCTA, 256, SM_TOTAL>>>(x);
    match_kernel<<<NHEAD, 1024>>>();
    dim3 g3(TOK / 128, NHEAD);
    gather_kernel<<<g3, 256>>>(emb, out);
}

// round 12
// speedup vs baseline: 9.1076x; 1.0191x over previous
#include <cuda_runtime.h>
#include <cuda_fp16.h>
#include <cstdint>

#define TOK   2048
#define CDIM  2048
#define NHEAD 32
#define DDIM  64
#define KR    1024

#define CTOK  256            // tokens per x tile
#define NTPM  128            // 8-col n-tiles per matrix
#define GSZ   8              // n-tiles per pipeline group
#define CHNT  48             // n-tiles per work unit (6 groups)
#define NUNIT 2048           // 8 tiles x 32 heads x 8 chunks
#define NCTA  296            // exactly 2 CTAs per SM on 148 SMs
#define NT_B  2048           // bytes per n-tile (hi/lo interleaved 16B)
#define GRP_B (GSZ * NT_B)   // 16 KB

#define SM_XPIT 68
#define SM_B    (CTOK * SM_XPIT * 4)          // 69632
#define SM_TOTAL (SM_B + 2 * GRP_B)           // 102400 -> 2 CTAs/SM

__device__ int g_row[NHEAD * TOK];
__device__ unsigned long long g_best[(size_t)3 * NHEAD * TOK];
// W fp16 hi/lo interleaved, fragment-major: [mat][head][ntl][ks][lane]{h0,h1,l0,l1}
__device__ __align__(16) uint8_t g_whf[(size_t)3 * NHEAD * NTPM * NT_B];   // 24 MB

// ---------------- helpers ----------------
static __device__ __forceinline__ uint32_t s2u(const void* p) {
    uint32_t a;
    asm("{ .reg .u64 t; cvta.to.shared.u64 t, %1; cvt.u32.u64 %0, t; }"
        : "=r"(a) : "l"(p));
    return a;
}
static __device__ __forceinline__ uint32_t h2u(__half2 h) {
    uint32_t u; asm("mov.b32 %0, %1;" : "=r"(u) : "r"(*(uint32_t*)&h)); return u;
}
static __device__ __forceinline__ void mma_f16(float* d, const uint32_t* a,
                                               uint32_t b0, uint32_t b1) {
    asm volatile("mma.sync.aligned.m16n8k16.row.col.f32.f16.f16.f32 "
                 "{%0,%1,%2,%3}, {%4,%5,%6,%7}, {%8,%9}, {%0,%1,%2,%3};"
                 : "+f"(d[0]), "+f"(d[1]), "+f"(d[2]), "+f"(d[3])
                 : "r"(a[0]), "r"(a[1]), "r"(a[2]), "r"(a[3]),
                   "r"(b0), "r"(b1));
}
static __device__ __forceinline__ void cp16(uint32_t d, const void* s) {
    asm volatile("cp.async.cg.shared.global [%0], [%1], 16;"
                 :: "r"(d), "l"(s) : "memory");
}
#define CP_COMMIT() asm volatile("cp.async.commit_group;" ::: "memory")
#define CP_WAIT1()  asm volatile("cp.async.wait_group 1;" ::: "memory")
#define CP_WAIT0()  asm volatile("cp.async.wait_group 0;" ::: "memory")

// split one float pair into packed fp16 hi / lo
static __device__ __forceinline__ void split2(float2 v, uint32_t& h, uint32_t& l) {
    __half2 hh = __float22half2_rn(v);
    float2 hf = __half22float2(hh);
    __half2 ll = __float22half2_rn(make_float2(v.x - hf.x, v.y - hf.y));
    h = h2u(hh); l = h2u(ll);
}
// orderable packing: larger logit wins; tie -> smaller col wins; 0 < any real
static __device__ __forceinline__ unsigned long long packcmp(float v, int col) {
    uint32_t b = __float_as_uint(v);
    uint32_t u = (b & 0x80000000u) ? ~b : (b | 0x80000000u);
    return ((unsigned long long)u << 32)
         | (unsigned long long)(0xFFFFFFFFu - (uint32_t)col);
}
static __device__ __forceinline__ int unpack_col(unsigned long long p) {
    return (int)(0xFFFFFFFFu - (uint32_t)(p & 0xFFFFFFFFull));
}

// ---------------------------------------------------------------------------
// Prepass: split W into fp16 hi/lo, fragment-major, hi/lo interleaved 16B.
// id bits: lane[0:5) ks[5:7) ntl[7:14) head[14:19) mat[19:21)
// Also zeroes g_best (first 196608 threads).
// ---------------------------------------------------------------------------
__global__ __launch_bounds__(256) void split_w_kernel(
    const float* __restrict__ wq, const float* __restrict__ wk,
    const float* __restrict__ wv)
{
    uint32_t id = blockIdx.x * 256u + threadIdx.x;
    if (id < 3u * NHEAD * TOK) g_best[id] = 0ull;
    uint32_t lane = id & 31u;
    uint32_t ks   = (id >> 5) & 3u;
    uint32_t ntl  = (id >> 7) & 127u;
    uint32_t head = (id >> 14) & 31u;
    uint32_t mat  = id >> 19;
    const float* W = (mat == 0) ? wq : (mat == 1) ? wk : wv;
    int col = (int)(ntl * 8 + (lane >> 2));
    int k0  = (int)(ks * 16 + 2 * (lane & 3));
    size_t off = ((size_t)head * KR + col) * DDIM + k0;
    float2 v0 = *reinterpret_cast<const float2*>(W + off);
    float2 v1 = *reinterpret_cast<const float2*>(W + off + 8);
    uint32_t h0, l0, h1, l1;
    split2(v0, h0, l0);
    split2(v1, h1, l1);
    uint4 o; o.x = h0; o.y = h1; o.z = l0; o.w = l1;
    *reinterpret_cast<uint4*>(g_whf + (size_t)id * 16) = o;
}

// ---------------------------------------------------------------------------
// Route kernel: 2-split fp16 mma argmax-GEMM, occupancy-exact partition.
// grid = 296 (2 CTAs/SM), block = 256. CTA i owns units [i*2048/296,(i+1)*2048/296).
// unit u: t8 = u>>8, head = (u>>3)&31, chunk = u&7 (48 n-tiles).
// Partial argmax merged via atomicMax on packed u64.
// ---------------------------------------------------------------------------
__global__ __launch_bounds__(256, 2) void tc_route_kernel(const float* __restrict__ x)
{
    extern __shared__ uint8_t smem[];
    float* xs = reinterpret_cast<float*>(smem);
    const uint32_t sbB = s2u(smem) + SM_B;

    const int tid = threadIdx.x, lane = tid & 31, wid = tid >> 5;
    const int u0 = (int)(((long long)blockIdx.x * NUNIT) / NCTA);
    const int u1 = (int)(((long long)(blockIdx.x + 1) * NUNIT) / NCTA);

    uint32_t ah[2][4][4], al[2][4][4];
    int cur_th = -1;
    int head = 0, t0 = 0;

    float bmax[4]; int bidx[4];
    #pragma unroll
    for (int sl = 0; sl < 4; ++sl) { bmax[sl] = -3.402823466e38f; bidx[sl] = 0; }

    for (int u = u0; u < u1; ++u) {
        const int th = u >> 3;
        const int chunk = u & 7;
        if (th != cur_th) {
            cur_th = th;
            head = th & 31;
            t0 = (th >> 5) * CTOK;
            __syncthreads();   // all warps done with previous compute / xs reads
            for (int i = tid; i < CTOK * 16; i += 256) {
                int t = i >> 4, c = i & 15;
                float4 v = *reinterpret_cast<const float4*>(
                    x + (size_t)(t0 + t) * CDIM + head * DDIM + c * 4);
                *reinterpret_cast<float4*>(&xs[t * SM_XPIT + c * 4]) = v;
            }
            __syncthreads();
            const int r0 = wid * 32 + (lane >> 2);
            #pragma unroll
            for (int mt = 0; mt < 2; ++mt)
                #pragma unroll
                for (int ks = 0; ks < 4; ++ks)
                    #pragma unroll
                    for (int e = 0; e < 4; ++e) {
                        int row = r0 + mt * 16 + (e & 1) * 8;
                        int kc  = ks * 16 + 2 * (lane & 3) + (e >> 1) * 8;
                        float2 v = *reinterpret_cast<const float2*>(
                            &xs[row * SM_XPIT + kc]);
                        split2(v, ah[mt][ks][e], al[mt][ks][e]);
                    }
        }

        const int F0u = chunk * CHNT;
        auto stage = [&](int gi) {
            int F0 = F0u + gi * GSZ;
            int mat = F0 >> 7, ntl0 = F0 & (NTPM - 1);
            const uint8_t* src = g_whf
                + (((size_t)mat * NHEAD + head) * NTPM + ntl0) * NT_B + tid * 16;
            uint32_t dst = sbB + (uint32_t)(gi & 1) * GRP_B + tid * 16;
            #pragma unroll
            for (int j = 0; j < 4; ++j)
                cp16(dst + j * 4096u, src + (size_t)j * 4096);
        };

        stage(0); CP_COMMIT();

        #pragma unroll 1
        for (int gi = 0; gi < CHNT / GSZ; ++gi) {
            if (gi + 1 < CHNT / GSZ) { stage(gi + 1); CP_COMMIT(); CP_WAIT1(); }
            else                     { CP_WAIT0(); }
            __syncthreads();

            const uint32_t bb = sbB + (uint32_t)(gi & 1) * GRP_B
                              + (uint32_t)lane * 16u;
            #pragma unroll 2
            for (int ntg = 0; ntg < GSZ; ++ntg) {
                const int F = F0u + gi * GSZ + ntg;
                float d0[4] = {0.f, 0.f, 0.f, 0.f};
                float d1[4] = {0.f, 0.f, 0.f, 0.f};
                const uint32_t tb = bb + (uint32_t)ntg * NT_B;
                #pragma unroll
                for (int ks = 0; ks < 4; ++ks) {
                    uint32_t bh0, bh1, bl0, bl1;
                    asm volatile("ld.shared.v4.b32 {%0,%1,%2,%3}, [%4];"
                                 : "=r"(bh0), "=r"(bh1), "=r"(bl0), "=r"(bl1)
                                 : "r"(tb + ks * 512u));
                    mma_f16(d0, ah[0][ks], bh0, bh1);   // hh
                    mma_f16(d0, al[0][ks], bh0, bh1);   // lh
                    mma_f16(d0, ah[0][ks], bl0, bl1);   // hl
                    mma_f16(d1, ah[1][ks], bh0, bh1);
                    mma_f16(d1, al[1][ks], bh0, bh1);
                    mma_f16(d1, ah[1][ks], bl0, bl1);
                }
                const int cb = (F & (NTPM - 1)) * 8 + 2 * (lane & 3);
                if (d0[0] > bmax[0]) { bmax[0] = d0[0]; bidx[0] = cb; }
                if (d0[1] > bmax[0]) { bmax[0] = d0[1]; bidx[0] = cb + 1; }
                if (d0[2] > bmax[1]) { bmax[1] = d0[2]; bidx[1] = cb; }
                if (d0[3] > bmax[1]) { bmax[1] = d0[3]; bidx[1] = cb + 1; }
                if (d1[0] > bmax[2]) { bmax[2] = d1[0]; bidx[2] = cb; }
                if (d1[1] > bmax[2]) { bmax[2] = d1[1]; bidx[2] = cb + 1; }
                if (d1[2] > bmax[3]) { bmax[3] = d1[2]; bidx[3] = cb; }
                if (d1[3] > bmax[3]) { bmax[3] = d1[3]; bidx[3] = cb + 1; }

                // flush at matrix boundary or unit end
                if ((F & (NTPM - 1)) == NTPM - 1 || F == F0u + CHNT - 1) {
                    const int mat = F >> 7;
                    unsigned long long* B =
                        g_best + ((size_t)mat * NHEAD + head) * TOK + t0;
                    #pragma unroll
                    for (int sl = 0; sl < 4; ++sl) {
                        float bv = bmax[sl]; int bi = bidx[sl];
                        #pragma unroll
                        for (int off = 1; off < 4; off <<= 1) {
                            float om = __shfl_xor_sync(0xffffffffu, bv, off, 32);
                            int   oi = __shfl_xor_sync(0xffffffffu, bi, off, 32);
                            if (om > bv || (om == bv && oi < bi)) {
                                bv = om; bi = oi;
                            }
                        }
                        if ((lane & 3) == 0) {
                            int row = wid * 32 + (lane >> 2)
                                    + (sl >> 1) * 16 + (sl & 1) * 8;
                            atomicMax(&B[row], packcmp(bv, bi));
                        }
                        bmax[sl] = -3.402823466e38f; bidx[sl] = 0;
                    }
                }
            }
            __syncthreads();
        }
    }
}

// ---------------------------------------------------------------------------
// tau matching via bucketed counting sort; ids decoded from g_best.
// grid = NHEAD, block = 1024 (short serial chains per phase).
// ---------------------------------------------------------------------------
__global__ __launch_bounds__(1024) void match_kernel()
{
    __shared__ int cnt[KR];
    __shared__ int bstart[KR + 1];
    __shared__ int kpos[TOK];
    __shared__ int wsum[32];

    const int m = blockIdx.x, tid = threadIdx.x;
    const int lane = tid & 31, wid = tid >> 5;
    const unsigned long long* bq = g_best + (size_t)(0 * NHEAD + m) * TOK;
    const unsigned long long* bk = g_best + (size_t)(1 * NHEAD + m) * TOK;
    const unsigned long long* bv = g_best + (size_t)(2 * NHEAD + m) * TOK;

    cnt[tid] = 0;
    int k0 = unpack_col(bk[tid]);
    int k1 = unpack_col(bk[tid + 1024]);
    __syncthreads();
    atomicAdd(&cnt[k0], 1);
    atomicAdd(&cnt[k1], 1);
    __syncthreads();

    // exclusive prefix over 1024 counters, 1 per thread
    int c = cnt[tid];
    int incl = c;
    #pragma unroll
    for (int off = 1; off < 32; off <<= 1) {
        int nv = __shfl_up_sync(0xffffffffu, incl, off, 32);
        if (lane >= off) incl += nv;
    }
    if (lane == 31) wsum[wid] = incl;
    __syncthreads();
    if (wid == 0) {
        int v = wsum[lane];
        int wincl = v;
        #pragma unroll
        for (int off = 1; off < 32; off <<= 1) {
            int nv = __shfl_up_sync(0xffffffffu, wincl, off, 32);
            if (lane >= off) wincl += nv;
        }
        wsum[lane] = wincl - v;   // exclusive
    }
    __syncthreads();
    int ex = incl - c + wsum[wid];
    bstart[tid] = ex;
    if (tid == 0) bstart[KR] = TOK;
    __syncthreads();
    cnt[tid] = ex;   // scatter cursor
    __syncthreads();

    {
        int p = atomicAdd(&cnt[k0], 1);
        kpos[p] = tid;
        int p1 = atomicAdd(&cnt[k1], 1);
        kpos[p1] = tid + 1024;
    }
    __syncthreads();

    // sort each bucket ascending (1 bucket per thread, avg size 2)
    {
        int lo = bstart[tid], hi = bstart[tid + 1];
        for (int i = lo + 1; i < hi; ++i) {
            int v = kpos[i], j = i - 1;
            while (j >= lo && kpos[j] > v) { kpos[j + 1] = kpos[j]; --j; }
            kpos[j + 1] = v;
        }
    }
    __syncthreads();

    #pragma unroll
    for (int h = 0; h < 2; ++h) {
        int t = tid + h * 1024;
        int q = unpack_col(bq[t]);
        int lo = bstart[q], hi = bstart[q + 1];
        int best = -1;
        for (int i = hi - 1; i >= lo; --i) {
            if (kpos[i] < t) { best = kpos[i]; break; }
        }
        g_row[m * TOK + t] = (best >= 0) ? (unpack_col(bv[best]) + 1) : 0;
    }
}

// ---------------------------------------------------------------------------
// Embedding gather. grid = (TOK/64, NHEAD) = (32, 32), block = 256.
// Rows staged to smem once (no redundant g_row loads, no dependent chains);
// each thread then issues 4 independent gather float4s (MLP 4).
// ---------------------------------------------------------------------------
__global__ __launch_bounds__(256) void gather_kernel(
    const float* __restrict__ emb, float* __restrict__ out)
{
    __shared__ int rows[64];
    const int m = blockIdx.y, t0 = blockIdx.x * 64;
    const int tid = threadIdx.x;
    if (tid < 64) rows[tid] = g_row[m * TOK + t0 + tid];
    __syncthreads();
    const float* E = emb + (size_t)m * (KR + 1) * DDIM;
    #pragma unroll
    for (int it = 0; it < 4; ++it) {
        int j = tid + it * 256;
        int t = j >> 4, dg = j & 15;
        int row = rows[t];
        float4 v;
        if (row) {
            v = *reinterpret_cast<const float4*>(E + (size_t)row * DDIM + dg * 4);
        } else {
            v = make_float4(0.f, 0.f, 0.f, 0.f);   // padding row is zero
        }
        *reinterpret_cast<float4*>(out + (size_t)(t0 + t) * CDIM + m * DDIM + dg * 4) = v;
    }
}

// ---------------------------------------------------------------------------
extern "C" void kernel_launch(void* const* d_in, const int* in_sizes, int n_in,
                              void* d_out, int out_size)
{
    (void)in_sizes; (void)n_in; (void)out_size;
    const float* x   = (const float*)d_in[0];
    const float* wq  = (const float*)d_in[1];
    const float* wk  = (const float*)d_in[2];
    const float* wv  = (const float*)d_in[3];
    const float* emb = (const float*)d_in[4];
    float* out = (float*)d_out;

    cudaFuncSetAttribute(tc_route_kernel,
                         cudaFuncAttributeMaxDynamicSharedMemorySize, SM_TOTAL);

    split_w_kernel<<<(3 * NHEAD * NTPM * 4 * 32) / 256, 256>>>(wq, wk, wv);
    tc_route_kernel<<<NCTA, 256, SM_TOTAL>>>(x);
    match_kernel<<<NHEAD, 1024>>>();
    dim3 g3(TOK / 64, NHEAD);
    gather_kernel<<<g3, 256>>>(emb, out);
}